// round 10
// baseline (speedup 1.0000x reference)
#include <cuda_runtime.h>
#include <cuda_bf16.h>
#include <cstdint>

#define T_LEN 512
#define B_SZ  256
#define I_SZ  128
#define H_SZ  256
#define G_SZ  768
#define L_NUM 6

#define M_ROWS (T_LEN * B_SZ)                  // 131072
#define TBH    ((size_t)T_LEN * B_SZ * H_SZ)   // 33554432
#define BH     (B_SZ * H_SZ)                   // 65536

typedef unsigned long long ull;

// ------------------------------ scratch -----------------------------------
__device__ float g_gx[(size_t)M_ROWS * G_SZ];
__device__ float g_buf[2ULL * TBH];
__device__ __nv_bfloat16 g_ahi[(size_t)M_ROWS * 256];
__device__ __nv_bfloat16 g_alo[(size_t)M_ROWS * 256];
__device__ __nv_bfloat16 g_whi[G_SZ * 256];
__device__ __nv_bfloat16 g_wlo[G_SZ * 256];
__device__ __align__(128) ull g_bar2[32][16];   // per-b-group barrier ctrs

// ------------------------------ helpers -----------------------------------
__device__ __forceinline__ ull pack2(float x, float y) {
    ull r; asm("mov.b64 %0, {%1, %2};" : "=l"(r) : "f"(x), "f"(y)); return r;
}
__device__ __forceinline__ float2 unpack2(ull v) {
    float2 r; asm("mov.b64 {%0, %1}, %2;" : "=f"(r.x), "=f"(r.y) : "l"(v)); return r;
}
__device__ __forceinline__ void fma2(ull& d, ull a, ull b) {
    asm("fma.rn.f32x2 %0, %1, %2, %0;" : "+l"(d) : "l"(a), "l"(b));
}
__device__ __forceinline__ ull add2(ull a, ull b) {
    ull r; asm("add.rn.f32x2 %0, %1, %2;" : "=l"(r) : "l"(a), "l"(b)); return r;
}
__device__ __forceinline__ float tanh_f(float x) {
    float y; asm("tanh.approx.f32 %0, %1;" : "=f"(y) : "f"(x)); return y;
}
__device__ __forceinline__ float sigmf(float x) {
    return 0.5f * tanh_f(0.5f * x) + 0.5f;
}
__device__ __forceinline__ uint32_t smem_u32(const void* p) {
    uint32_t a;
    asm("{ .reg .u64 t; cvta.to.shared.u64 t, %1; cvt.u32.u64 %0, t; }"
        : "=r"(a) : "l"(p));
    return a;
}

// 4-CTA barrier per b-group (release arrive + acquire poll, monotonic ctr).
__device__ __forceinline__ void bg_barrier(int bg) {
    __syncthreads();
    if (threadIdx.x == 0) {
        ull* ctr = &g_bar2[bg][0];
        ull old;
        asm volatile("atom.release.gpu.global.add.u64 %0, [%1], 1;"
                     : "=l"(old) : "l"(ctr) : "memory");
        ull target = ((old + 1ULL + 3ULL) >> 2) << 2;
        if (old + 1ULL != target) {
            ull v;
            do {
                asm volatile("ld.acquire.gpu.global.u64 %0, [%1];"
                             : "=l"(v) : "l"(ctr) : "memory");
            } while (v < target);
        }
    }
    __syncthreads();
}

// ------------------------- fp32 -> bf16 hi/lo split -------------------------
__device__ __forceinline__ uint32_t bpack(float a, float b, bool lo) {
    __nv_bfloat16 ah = __float2bfloat16(a);
    __nv_bfloat16 bh = __float2bfloat16(b);
    if (lo) {
        ah = __float2bfloat16(a - __bfloat162float(ah));
        bh = __float2bfloat16(b - __bfloat162float(bh));
    }
    return (uint32_t)__bfloat16_as_ushort(ah) |
           ((uint32_t)__bfloat16_as_ushort(bh) << 16);
}

__global__ void conv_kernel(const float* __restrict__ A, const float* __restrict__ W,
                            int mk4, int wk4)
{
    int i = blockIdx.x * 256 + threadIdx.x;
    if (i < mk4) {
        float4 v = ((const float4*)A)[i];
        ((uint2*)g_ahi)[i] = make_uint2(bpack(v.x, v.y, false), bpack(v.z, v.w, false));
        ((uint2*)g_alo)[i] = make_uint2(bpack(v.x, v.y, true),  bpack(v.z, v.w, true));
    } else if (i < mk4 + wk4) {
        int j = i - mk4;
        float4 v = ((const float4*)W)[j];
        ((uint2*)g_whi)[j] = make_uint2(bpack(v.x, v.y, false), bpack(v.z, v.w, false));
        ((uint2*)g_wlo)[j] = make_uint2(bpack(v.x, v.y, true),  bpack(v.z, v.w, true));
    }
}

// ------------------------ mma.sync bf16 GEMM (proven) -----------------------
#define GROW 72
#define GTILE (128 * GROW * 2)
#define GSM_TOTAL (4 * GTILE)

__device__ __forceinline__ void ldmx4(uint32_t* r, uint32_t addr) {
    asm volatile("ldmatrix.sync.aligned.m8n8.x4.shared.b16 {%0,%1,%2,%3}, [%4];"
                 : "=r"(r[0]), "=r"(r[1]), "=r"(r[2]), "=r"(r[3]) : "r"(addr));
}
__device__ __forceinline__ void mma16816(float* d, const uint32_t* a,
                                         uint32_t b0, uint32_t b1) {
    asm volatile(
        "mma.sync.aligned.m16n8k16.row.col.f32.bf16.bf16.f32 "
        "{%0,%1,%2,%3}, {%4,%5,%6,%7}, {%8,%9}, {%0,%1,%2,%3};"
        : "+f"(d[0]), "+f"(d[1]), "+f"(d[2]), "+f"(d[3])
        : "r"(a[0]), "r"(a[1]), "r"(a[2]), "r"(a[3]), "r"(b0), "r"(b1));
}

__global__ void __launch_bounds__(256, 2)
gemm_mma_kernel(const __nv_bfloat16* __restrict__ Ahi,
                const __nv_bfloat16* __restrict__ Alo,
                const __nv_bfloat16* __restrict__ Whi,
                const __nv_bfloat16* __restrict__ Wlo,
                const float* __restrict__ bias,
                float* __restrict__ C, int K)
{
    extern __shared__ char gsm[];
    char* tAH = gsm;
    char* tAL = gsm + GTILE;
    char* tBH = gsm + 2 * GTILE;
    char* tBL = gsm + 3 * GTILE;

    const int tid = threadIdx.x;
    const int wid = tid >> 5;
    const int lane = tid & 31;
    const int wm = wid & 1;
    const int wn = wid >> 1;
    const int n0 = blockIdx.x * 128;
    const int m0 = blockIdx.y * 128;

    float acc[4][4][4];
    #pragma unroll
    for (int i = 0; i < 4; ++i)
        #pragma unroll
        for (int j = 0; j < 4; ++j)
            #pragma unroll
            for (int q = 0; q < 4; ++q) acc[i][j][q] = 0.0f;

    const int lrow = lane & 15;
    const int lkg  = (lane >> 4) * 8;

    const int nch = K >> 6;
    for (int c = 0; c < nch; ++c) {
        #pragma unroll
        for (int p = 0; p < 4; ++p) {
            int idx = p * 256 + tid;
            int row = idx >> 3;
            int k8  = (idx & 7) * 8;
            size_t ga = (size_t)(m0 + row) * K + c * 64 + k8;
            size_t gb = (size_t)(n0 + row) * K + c * 64 + k8;
            uint32_t so = (uint32_t)(row * (GROW * 2) + k8 * 2);
            *(uint4*)(tAH + so) = *(const uint4*)(Ahi + ga);
            *(uint4*)(tAL + so) = *(const uint4*)(Alo + ga);
            *(uint4*)(tBH + so) = *(const uint4*)(Whi + gb);
            *(uint4*)(tBL + so) = *(const uint4*)(Wlo + gb);
        }
        __syncthreads();

        #pragma unroll
        for (int pass = 0; pass < 3; ++pass) {
            const char* At = (pass == 2) ? tAL : tAH;
            const char* Bt = (pass == 1) ? tBL : tBH;
            const uint32_t abase = smem_u32(At) +
                (uint32_t)((wm * 64 + lrow) * (GROW * 2) + lkg * 2);
            const uint32_t bbase = smem_u32(Bt) +
                (uint32_t)((wn * 32 + lrow) * (GROW * 2) + lkg * 2);

            #pragma unroll
            for (int k16 = 0; k16 < 4; ++k16) {
                uint32_t a[4][4], b[2][4];
                #pragma unroll
                for (int mt = 0; mt < 4; ++mt)
                    ldmx4(a[mt], abase + mt * 16 * (GROW * 2) + k16 * 32);
                #pragma unroll
                for (int bh = 0; bh < 2; ++bh)
                    ldmx4(b[bh], bbase + bh * 16 * (GROW * 2) + k16 * 32);
                #pragma unroll
                for (int mt = 0; mt < 4; ++mt) {
                    #pragma unroll
                    for (int nt = 0; nt < 4; ++nt) {
                        int bh = nt >> 1, sub = nt & 1;
                        mma16816(acc[mt][nt], a[mt], b[bh][sub], b[bh][sub + 2]);
                    }
                }
            }
        }
        __syncthreads();
    }

    #pragma unroll
    for (int nt = 0; nt < 4; ++nt) {
        int col = n0 + wn * 32 + nt * 8 + (lane & 3) * 2;
        float2 bv = *(const float2*)(bias + col);
        #pragma unroll
        for (int mt = 0; mt < 4; ++mt) {
            int row = m0 + wm * 64 + mt * 16 + (lane >> 2);
            float2 o0 = { acc[mt][nt][0] + bv.x, acc[mt][nt][1] + bv.y };
            float2 o1 = { acc[mt][nt][2] + bv.x, acc[mt][nt][3] + bv.y };
            *(float2*)(C + (size_t)row * G_SZ + col) = o0;
            *(float2*)(C + (size_t)(row + 8) * G_SZ + col) = o1;
        }
    }
}

// ---------------------------------------------------------------------------
// Persistent recurrent scan: 32 b-groups x 4 h-groups (4-CTA coupling).
// W slice = 192 gate-cols x 256 k in smem (196.6 KB). 256 threads, k-split.
// Thread map (per k-half): 8 rows x 16 col-groups. gx[t+1] prefetched
// before the barrier. finals written at t=511.
// ---------------------------------------------------------------------------
#define SCAN_PAD  260
#define SCAN_WS   (192 * 256)
#define SCAN_HS   (8 * SCAN_PAD)
#define SCAN_SMEM ((SCAN_WS + SCAN_HS) * 4 + 128 * 6 * 8)   // 211072 B

__global__ void __launch_bounds__(256)
gru_scan_kernel(const float* __restrict__ Whh, const float* __restrict__ bhh,
                const float* __restrict__ gx, const float* __restrict__ hinit,
                float* __restrict__ out, float* __restrict__ finals)
{
    extern __shared__ float smem[];
    float* Ws = smem;                                 // [256][192] k-major
    float* hs = smem + SCAN_WS;                       // [8][260]
    ull*   red = (ull*)(smem + SCAN_WS + SCAN_HS);    // [128][6]

    const int tid = threadIdx.x;
    const int bg = blockIdx.x >> 2;      // 0..31
    const int hg = blockIdx.x & 3;       // 0..3
    const int b0 = bg * 8;
    const int h0 = hg * 64;

    // W slice transpose: Ws[k*192 + gt*64 + col] = Whh[(gt*256 + h0 + col)][k]
    for (int idx = tid; idx < 192 * 256; idx += 256) {
        int j = idx >> 8;            // 0..191
        int k = idx & 255;
        int gt = j >> 6, col = j & 63;
        Ws[k * 192 + j] = Whh[(size_t)(gt * 256 + h0 + col) * 256 + k];
    }

    const int ks = tid >> 7;             // 0/1 : k-half
    const int tl = tid & 127;
    const int r  = tl & 7;               // row 0..7
    const int cg = tl >> 3;              // col-group 0..15
    const int cb = h0 + cg * 4;          // global h-column base
    const int b  = b0 + r;
    const int kbase = ks * 128;

    float4 brv = *(const float4*)(bhh + cb);
    float4 bzv = *(const float4*)(bhh + 256 + cb);
    float4 bnv = *(const float4*)(bhh + 512 + cb);

    // prefetch gx for t=0 (finalizer half only)
    float4 ir, iz, inn;
    if (ks == 0) {
        const float* gxr = gx + (size_t)b * G_SZ;
        ir  = *(const float4*)(gxr + cb);
        iz  = *(const float4*)(gxr + 256 + cb);
        inn = *(const float4*)(gxr + 512 + cb);
    }

    __syncthreads();

    for (int t = 0; t < T_LEN; ++t) {
        // stage h tile [8 x 256] -> hs (ld.cv: peers wrote via L2)
        const float4* hsrc = (t == 0)
            ? (const float4*)(hinit + (size_t)b0 * 256)
            : (const float4*)(out + ((size_t)(t - 1) * B_SZ + b0) * 256);
        #pragma unroll
        for (int p = 0; p < 2; ++p) {
            int f = tid + p * 256;       // 0..511
            int row = f >> 6;
            int kf = f & 63;
            float4 v = __ldcv(hsrc + row * 64 + kf);
            *(float4*)(hs + row * SCAN_PAD + kf * 4) = v;
        }
        __syncthreads();

        ull aR0 = 0, aR1 = 0, aZ0 = 0, aZ1 = 0, aN0 = 0, aN1 = 0;
        const float* hr = hs + r * SCAN_PAD;
        const float* wp = Ws + cg * 4 + kbase * 192;

        #pragma unroll 4
        for (int k0 = 0; k0 < 128; k0 += 4) {
            float4 h4 = *(const float4*)(hr + kbase + k0);
            #pragma unroll
            for (int u = 0; u < 4; ++u) {
                float a = (u == 0) ? h4.x : (u == 1) ? h4.y : (u == 2) ? h4.z : h4.w;
                ull a2 = pack2(a, a);
                const float* wk = wp + (k0 + u) * 192;
                ulonglong2 wr = *(const ulonglong2*)(wk);
                ulonglong2 wz = *(const ulonglong2*)(wk + 64);
                ulonglong2 wn = *(const ulonglong2*)(wk + 128);
                fma2(aR0, a2, wr.x); fma2(aR1, a2, wr.y);
                fma2(aZ0, a2, wz.x); fma2(aZ1, a2, wz.y);
                fma2(aN0, a2, wn.x); fma2(aN1, a2, wn.y);
            }
        }

        if (ks == 1) {
            ull* rp = &red[tl * 6];
            rp[0] = aR0; rp[1] = aR1; rp[2] = aZ0;
            rp[3] = aZ1; rp[4] = aN0; rp[5] = aN1;
        }
        __syncthreads();

        if (ks == 0) {
            const ull* rp = &red[tl * 6];
            aR0 = add2(aR0, rp[0]); aR1 = add2(aR1, rp[1]);
            aZ0 = add2(aZ0, rp[2]); aZ1 = add2(aZ1, rp[3]);
            aN0 = add2(aN0, rp[4]); aN1 = add2(aN1, rp[5]);

            float4 hp = *(const float4*)(hr + cb);
            float2 r01 = unpack2(aR0), r23 = unpack2(aR1);
            float2 z01 = unpack2(aZ0), z23 = unpack2(aZ1);
            float2 n01 = unpack2(aN0), n23 = unpack2(aN1);

            float rg0 = sigmf(ir.x + r01.x + brv.x);
            float rg1 = sigmf(ir.y + r01.y + brv.y);
            float rg2 = sigmf(ir.z + r23.x + brv.z);
            float rg3 = sigmf(ir.w + r23.y + brv.w);
            float zg0 = sigmf(iz.x + z01.x + bzv.x);
            float zg1 = sigmf(iz.y + z01.y + bzv.y);
            float zg2 = sigmf(iz.z + z23.x + bzv.z);
            float zg3 = sigmf(iz.w + z23.y + bzv.w);
            float ng0 = tanh_f(inn.x + rg0 * (n01.x + bnv.x));
            float ng1 = tanh_f(inn.y + rg1 * (n01.y + bnv.y));
            float ng2 = tanh_f(inn.z + rg2 * (n23.x + bnv.z));
            float ng3 = tanh_f(inn.w + rg3 * (n23.y + bnv.w));

            float4 hv;
            hv.x = (1.0f - zg0) * ng0 + zg0 * hp.x;
            hv.y = (1.0f - zg1) * ng1 + zg1 * hp.y;
            hv.z = (1.0f - zg2) * ng2 + zg2 * hp.z;
            hv.w = (1.0f - zg3) * ng3 + zg3 * hp.w;

            *(float4*)(out + ((size_t)t * B_SZ + b) * 256 + cb) = hv;
            if (t == T_LEN - 1)
                *(float4*)(finals + (size_t)b * 256 + cb) = hv;

            // prefetch gx for t+1 BEFORE the barrier (hides DRAM latency)
            if (t + 1 < T_LEN) {
                const float* gxr = gx + ((size_t)(t + 1) * B_SZ + b) * G_SZ;
                ir  = *(const float4*)(gxr + cb);
                iz  = *(const float4*)(gxr + 256 + cb);
                inn = *(const float4*)(gxr + 512 + cb);
            }
        }

        if (t != T_LEN - 1) bg_barrier(bg);
        else __syncthreads();
    }
}

// ---------------------------------------------------------------------------
extern "C" void kernel_launch(void* const* d_in, const int* in_sizes, int n_in,
                              void* d_out, int out_size)
{
    const float* x     = (const float*)d_in[0];
    const float* h0    = (const float*)d_in[1];
    const float* Wih0  = (const float*)d_in[2];
    const float* Wih   = (const float*)d_in[3];
    const float* Whh   = (const float*)d_in[4];
    const float* bih   = (const float*)d_in[5];
    const float* bhh   = (const float*)d_in[6];
    float* out = (float*)d_out;

    float *gx_p = nullptr, *buf_p = nullptr;
    __nv_bfloat16 *ahi_p, *alo_p, *whi_p, *wlo_p;
    cudaGetSymbolAddress((void**)&gx_p,  g_gx);
    cudaGetSymbolAddress((void**)&buf_p, g_buf);
    cudaGetSymbolAddress((void**)&ahi_p, g_ahi);
    cudaGetSymbolAddress((void**)&alo_p, g_alo);
    cudaGetSymbolAddress((void**)&whi_p, g_whi);
    cudaGetSymbolAddress((void**)&wlo_p, g_wlo);

    cudaFuncSetAttribute(gru_scan_kernel,
                         cudaFuncAttributeMaxDynamicSharedMemorySize, SCAN_SMEM);
    cudaFuncSetAttribute(gemm_mma_kernel,
                         cudaFuncAttributeMaxDynamicSharedMemorySize, GSM_TOTAL);

    for (int l = 0; l < L_NUM; ++l) {
        const float* in  = (l == 0) ? x   : buf_p + (size_t)((l - 1) & 1) * TBH;
        float*       lo  = (l == L_NUM - 1) ? out : buf_p + (size_t)(l & 1) * TBH;
        const int    K   = (l == 0) ? I_SZ : H_SZ;
        const float* Wi  = (l == 0) ? Wih0 : Wih + (size_t)(l - 1) * G_SZ * H_SZ;
        const float* Wh  = Whh + (size_t)l * G_SZ * H_SZ;
        const float* bi  = bih + (size_t)l * G_SZ;
        const float* bh  = bhh + (size_t)l * G_SZ;

        int mk4 = M_ROWS * K / 4, wk4 = G_SZ * K / 4;
        conv_kernel<<<(mk4 + wk4 + 255) / 256, 256>>>(in, Wi, mk4, wk4);

        dim3 gg(G_SZ / 128, M_ROWS / 128);
        gemm_mma_kernel<<<gg, 256, GSM_TOTAL>>>(ahi_p, alo_p, whi_p, wlo_p,
                                                bi, gx_p, K);

        gru_scan_kernel<<<128, 256, SCAN_SMEM>>>(Wh, bh, gx_p,
                                                 h0 + (size_t)l * BH, lo,
                                                 out + TBH + (size_t)l * BH);
    }
}

// round 11
// speedup vs baseline: 1.0144x; 1.0144x over previous
#include <cuda_runtime.h>
#include <cuda_bf16.h>
#include <cstdint>

#define T_LEN 512
#define B_SZ  256
#define I_SZ  128
#define H_SZ  256
#define G_SZ  768
#define L_NUM 6

#define M_ROWS (T_LEN * B_SZ)                  // 131072
#define TBH    ((size_t)T_LEN * B_SZ * H_SZ)   // 33554432
#define BH     (B_SZ * H_SZ)                   // 65536

typedef unsigned long long ull;

// ------------------------------ scratch -----------------------------------
__device__ float g_gx[(size_t)M_ROWS * G_SZ];
__device__ float g_buf[2ULL * TBH];
__device__ __nv_bfloat16 g_ahi[(size_t)M_ROWS * 256];
__device__ __nv_bfloat16 g_alo[(size_t)M_ROWS * 256];
__device__ __nv_bfloat16 g_whi[G_SZ * 256];
__device__ __nv_bfloat16 g_wlo[G_SZ * 256];

// ------------------------------ helpers -----------------------------------
__device__ __forceinline__ ull pack2(float x, float y) {
    ull r; asm("mov.b64 %0, {%1, %2};" : "=l"(r) : "f"(x), "f"(y)); return r;
}
__device__ __forceinline__ float2 unpack2(ull v) {
    float2 r; asm("mov.b64 {%0, %1}, %2;" : "=f"(r.x), "=f"(r.y) : "l"(v)); return r;
}
__device__ __forceinline__ void fma2(ull& d, ull a, ull b) {
    asm("fma.rn.f32x2 %0, %1, %2, %0;" : "+l"(d) : "l"(a), "l"(b));
}
__device__ __forceinline__ ull add2(ull a, ull b) {
    ull r; asm("add.rn.f32x2 %0, %1, %2;" : "=l"(r) : "l"(a), "l"(b)); return r;
}
__device__ __forceinline__ float tanh_f(float x) {
    float y; asm("tanh.approx.f32 %0, %1;" : "=f"(y) : "f"(x)); return y;
}
__device__ __forceinline__ float sigmf(float x) {
    return 0.5f * tanh_f(0.5f * x) + 0.5f;
}
__device__ __forceinline__ uint32_t smem_u32(const void* p) {
    uint32_t a;
    asm("{ .reg .u64 t; cvta.to.shared.u64 t, %1; cvt.u32.u64 %0, t; }"
        : "=r"(a) : "l"(p));
    return a;
}

// ------------------------- fp32 -> bf16 hi/lo split -------------------------
__device__ __forceinline__ uint32_t bpack(float a, float b, bool lo) {
    __nv_bfloat16 ah = __float2bfloat16(a);
    __nv_bfloat16 bh = __float2bfloat16(b);
    if (lo) {
        ah = __float2bfloat16(a - __bfloat162float(ah));
        bh = __float2bfloat16(b - __bfloat162float(bh));
    }
    return (uint32_t)__bfloat16_as_ushort(ah) |
           ((uint32_t)__bfloat16_as_ushort(bh) << 16);
}

__global__ void conv_kernel(const float* __restrict__ A, const float* __restrict__ W,
                            int mk4, int wk4)
{
    int i = blockIdx.x * 256 + threadIdx.x;
    if (i < mk4) {
        float4 v = ((const float4*)A)[i];
        ((uint2*)g_ahi)[i] = make_uint2(bpack(v.x, v.y, false), bpack(v.z, v.w, false));
        ((uint2*)g_alo)[i] = make_uint2(bpack(v.x, v.y, true),  bpack(v.z, v.w, true));
    } else if (i < mk4 + wk4) {
        int j = i - mk4;
        float4 v = ((const float4*)W)[j];
        ((uint2*)g_whi)[j] = make_uint2(bpack(v.x, v.y, false), bpack(v.z, v.w, false));
        ((uint2*)g_wlo)[j] = make_uint2(bpack(v.x, v.y, true),  bpack(v.z, v.w, true));
    }
}

// ------------------------ mma.sync bf16 GEMM (proven) -----------------------
#define GROW 72
#define GTILE (128 * GROW * 2)
#define GSM_TOTAL (4 * GTILE)

__device__ __forceinline__ void ldmx4(uint32_t* r, uint32_t addr) {
    asm volatile("ldmatrix.sync.aligned.m8n8.x4.shared.b16 {%0,%1,%2,%3}, [%4];"
                 : "=r"(r[0]), "=r"(r[1]), "=r"(r[2]), "=r"(r[3]) : "r"(addr));
}
__device__ __forceinline__ void mma16816(float* d, const uint32_t* a,
                                         uint32_t b0, uint32_t b1) {
    asm volatile(
        "mma.sync.aligned.m16n8k16.row.col.f32.bf16.bf16.f32 "
        "{%0,%1,%2,%3}, {%4,%5,%6,%7}, {%8,%9}, {%0,%1,%2,%3};"
        : "+f"(d[0]), "+f"(d[1]), "+f"(d[2]), "+f"(d[3])
        : "r"(a[0]), "r"(a[1]), "r"(a[2]), "r"(a[3]), "r"(b0), "r"(b1));
}

__global__ void __launch_bounds__(256, 2)
gemm_mma_kernel(const __nv_bfloat16* __restrict__ Ahi,
                const __nv_bfloat16* __restrict__ Alo,
                const __nv_bfloat16* __restrict__ Whi,
                const __nv_bfloat16* __restrict__ Wlo,
                const float* __restrict__ bias,
                float* __restrict__ C, int K)
{
    extern __shared__ char gsm[];
    char* tAH = gsm;
    char* tAL = gsm + GTILE;
    char* tBH = gsm + 2 * GTILE;
    char* tBL = gsm + 3 * GTILE;

    const int tid = threadIdx.x;
    const int wid = tid >> 5;
    const int lane = tid & 31;
    const int wm = wid & 1;
    const int wn = wid >> 1;
    const int n0 = blockIdx.x * 128;
    const int m0 = blockIdx.y * 128;

    float acc[4][4][4];
    #pragma unroll
    for (int i = 0; i < 4; ++i)
        #pragma unroll
        for (int j = 0; j < 4; ++j)
            #pragma unroll
            for (int q = 0; q < 4; ++q) acc[i][j][q] = 0.0f;

    const int lrow = lane & 15;
    const int lkg  = (lane >> 4) * 8;

    const int nch = K >> 6;
    for (int c = 0; c < nch; ++c) {
        #pragma unroll
        for (int p = 0; p < 4; ++p) {
            int idx = p * 256 + tid;
            int row = idx >> 3;
            int k8  = (idx & 7) * 8;
            size_t ga = (size_t)(m0 + row) * K + c * 64 + k8;
            size_t gb = (size_t)(n0 + row) * K + c * 64 + k8;
            uint32_t so = (uint32_t)(row * (GROW * 2) + k8 * 2);
            *(uint4*)(tAH + so) = *(const uint4*)(Ahi + ga);
            *(uint4*)(tAL + so) = *(const uint4*)(Alo + ga);
            *(uint4*)(tBH + so) = *(const uint4*)(Whi + gb);
            *(uint4*)(tBL + so) = *(const uint4*)(Wlo + gb);
        }
        __syncthreads();

        #pragma unroll
        for (int pass = 0; pass < 3; ++pass) {
            const char* At = (pass == 2) ? tAL : tAH;
            const char* Bt = (pass == 1) ? tBL : tBH;
            const uint32_t abase = smem_u32(At) +
                (uint32_t)((wm * 64 + lrow) * (GROW * 2) + lkg * 2);
            const uint32_t bbase = smem_u32(Bt) +
                (uint32_t)((wn * 32 + lrow) * (GROW * 2) + lkg * 2);

            #pragma unroll
            for (int k16 = 0; k16 < 4; ++k16) {
                uint32_t a[4][4], b[2][4];
                #pragma unroll
                for (int mt = 0; mt < 4; ++mt)
                    ldmx4(a[mt], abase + mt * 16 * (GROW * 2) + k16 * 32);
                #pragma unroll
                for (int bh = 0; bh < 2; ++bh)
                    ldmx4(b[bh], bbase + bh * 16 * (GROW * 2) + k16 * 32);
                #pragma unroll
                for (int mt = 0; mt < 4; ++mt) {
                    #pragma unroll
                    for (int nt = 0; nt < 4; ++nt) {
                        int bh = nt >> 1, sub = nt & 1;
                        mma16816(acc[mt][nt], a[mt], b[bh][sub], b[bh][sub + 2]);
                    }
                }
            }
        }
        __syncthreads();
    }

    #pragma unroll
    for (int nt = 0; nt < 4; ++nt) {
        int col = n0 + wn * 32 + nt * 8 + (lane & 3) * 2;
        float2 bv = *(const float2*)(bias + col);
        #pragma unroll
        for (int mt = 0; mt < 4; ++mt) {
            int row = m0 + wm * 64 + mt * 16 + (lane >> 2);
            float2 o0 = { acc[mt][nt][0] + bv.x, acc[mt][nt][1] + bv.y };
            float2 o1 = { acc[mt][nt][2] + bv.x, acc[mt][nt][3] + bv.y };
            *(float2*)(C + (size_t)row * G_SZ + col) = o0;
            *(float2*)(C + (size_t)(row + 8) * G_SZ + col) = o1;
        }
    }
}

// ---------------------------------------------------------------------------
// Persistent recurrent scan: 32 clusters of 4 CTAs (one per b-group).
// h exchanged via DSMEM multicast (mapa + st.shared::cluster) into a
// double-buffered smem tile; barrier.cluster replaces the L2 atomic chain.
// W slice = 192 gate-cols x 256 k (196.6 KB smem). 256 threads, k-split.
// ---------------------------------------------------------------------------
#define SCAN_PAD  260
#define SCAN_WS   (192 * 256)
#define SCAN_HS1  (8 * SCAN_PAD)
#define SCAN_SMEM ((SCAN_WS + 2 * SCAN_HS1) * 4 + 128 * 6 * 8)   // 219392 B

__global__ void __launch_bounds__(256) __cluster_dims__(4, 1, 1)
gru_scan_kernel(const float* __restrict__ Whh, const float* __restrict__ bhh,
                const float* __restrict__ gx, const float* __restrict__ hinit,
                float* __restrict__ out, float* __restrict__ finals)
{
    extern __shared__ float smem[];
    float* Ws  = smem;                          // [256][192] k-major
    float* hsA = smem + SCAN_WS;                // [8][260]
    float* hsB = hsA + SCAN_HS1;                // [8][260]
    ull*   red = (ull*)(hsB + SCAN_HS1);        // [128][6]

    const int tid = threadIdx.x;
    const int bg = blockIdx.x >> 2;      // 0..31 : cluster id
    const int hg = blockIdx.x & 3;       // 0..3  : rank in cluster
    const int b0 = bg * 8;
    const int h0 = hg * 64;

    // W slice transpose: Ws[k*192 + gt*64 + col] = Whh[(gt*256 + h0 + col)][k]
    for (int idx = tid; idx < 192 * 256; idx += 256) {
        int j = idx >> 8;
        int k = idx & 255;
        int gt = j >> 6, col = j & 63;
        Ws[k * 192 + j] = Whh[(size_t)(gt * 256 + h0 + col) * 256 + k];
    }

    // initial h tile into hsA (each CTA loads the full 8x256 slice)
    for (int f = tid; f < 512; f += 256) {
        int row = f >> 6;
        int kf = (f & 63) << 2;
        *(float4*)(hsA + row * SCAN_PAD + kf) =
            *(const float4*)(hinit + (size_t)(b0 + row) * 256 + kf);
    }

    const int ks = tid >> 7;             // 0/1 : k-half
    const int tl = tid & 127;
    const int r  = tl & 7;               // row 0..7
    const int cg = tl >> 3;              // col-group 0..15
    const int cb = h0 + cg * 4;          // global h-column base
    const int b  = b0 + r;
    const int kbase = ks * 128;

    float4 brv = *(const float4*)(bhh + cb);
    float4 bzv = *(const float4*)(bhh + 256 + cb);
    float4 bnv = *(const float4*)(bhh + 512 + cb);

    // local smem byte addresses of this thread's h slot (both buffers)
    const uint32_t slotA = smem_u32(hsA) + (uint32_t)(r * SCAN_PAD + cb) * 4u;
    const uint32_t slotB = smem_u32(hsB) + (uint32_t)(r * SCAN_PAD + cb) * 4u;

    // prefetch gx for t=0 (finalizer half only)
    float4 ir, iz, inn;
    if (ks == 0) {
        const float* gxr = gx + (size_t)b * G_SZ;
        ir  = *(const float4*)(gxr + cb);
        iz  = *(const float4*)(gxr + 256 + cb);
        inn = *(const float4*)(gxr + 512 + cb);
    }

    __syncthreads();
    asm volatile("barrier.cluster.arrive.aligned;" ::: "memory");
    asm volatile("barrier.cluster.wait.aligned;"   ::: "memory");

    for (int t = 0; t < T_LEN; ++t) {
        const float* cur = (t & 1) ? hsB : hsA;
        const float* hr = cur + r * SCAN_PAD;
        const float* wp = Ws + cg * 4 + kbase * 192;

        ull aR0 = 0, aR1 = 0, aZ0 = 0, aZ1 = 0, aN0 = 0, aN1 = 0;

        #pragma unroll 4
        for (int k0 = 0; k0 < 128; k0 += 4) {
            float4 h4 = *(const float4*)(hr + kbase + k0);
            #pragma unroll
            for (int u = 0; u < 4; ++u) {
                float a = (u == 0) ? h4.x : (u == 1) ? h4.y : (u == 2) ? h4.z : h4.w;
                ull a2 = pack2(a, a);
                const float* wk = wp + (k0 + u) * 192;
                ulonglong2 wr = *(const ulonglong2*)(wk);
                ulonglong2 wz = *(const ulonglong2*)(wk + 64);
                ulonglong2 wn = *(const ulonglong2*)(wk + 128);
                fma2(aR0, a2, wr.x); fma2(aR1, a2, wr.y);
                fma2(aZ0, a2, wz.x); fma2(aZ1, a2, wz.y);
                fma2(aN0, a2, wn.x); fma2(aN1, a2, wn.y);
            }
        }

        // combine k-halves
        if (ks == 1) {
            ull* rp = &red[tl * 6];
            rp[0] = aR0; rp[1] = aR1; rp[2] = aZ0;
            rp[3] = aZ1; rp[4] = aN0; rp[5] = aN1;
        }
        __syncthreads();

        if (ks == 0) {
            const ull* rp = &red[tl * 6];
            aR0 = add2(aR0, rp[0]); aR1 = add2(aR1, rp[1]);
            aZ0 = add2(aZ0, rp[2]); aZ1 = add2(aZ1, rp[3]);
            aN0 = add2(aN0, rp[4]); aN1 = add2(aN1, rp[5]);

            float4 hp = *(const float4*)(hr + cb);
            float2 r01 = unpack2(aR0), r23 = unpack2(aR1);
            float2 z01 = unpack2(aZ0), z23 = unpack2(aZ1);
            float2 n01 = unpack2(aN0), n23 = unpack2(aN1);

            float rg0 = sigmf(ir.x + r01.x + brv.x);
            float rg1 = sigmf(ir.y + r01.y + brv.y);
            float rg2 = sigmf(ir.z + r23.x + brv.z);
            float rg3 = sigmf(ir.w + r23.y + brv.w);
            float zg0 = sigmf(iz.x + z01.x + bzv.x);
            float zg1 = sigmf(iz.y + z01.y + bzv.y);
            float zg2 = sigmf(iz.z + z23.x + bzv.z);
            float zg3 = sigmf(iz.w + z23.y + bzv.w);
            float ng0 = tanh_f(inn.x + rg0 * (n01.x + bnv.x));
            float ng1 = tanh_f(inn.y + rg1 * (n01.y + bnv.y));
            float ng2 = tanh_f(inn.z + rg2 * (n23.x + bnv.z));
            float ng3 = tanh_f(inn.w + rg3 * (n23.y + bnv.w));

            float4 hv;
            hv.x = (1.0f - zg0) * ng0 + zg0 * hp.x;
            hv.y = (1.0f - zg1) * ng1 + zg1 * hp.y;
            hv.z = (1.0f - zg2) * ng2 + zg2 * hp.z;
            hv.w = (1.0f - zg3) * ng3 + zg3 * hp.w;

            *(float4*)(out + ((size_t)t * B_SZ + b) * 256 + cb) = hv;

            if (t != T_LEN - 1) {
                // multicast own 4 h values into next-step buffer of all 4 CTAs
                ull q0 = pack2(hv.x, hv.y);
                ull q1 = pack2(hv.z, hv.w);
                uint32_t dst = (t & 1) ? slotA : slotB;
                #pragma unroll
                for (int p = 0; p < 4; ++p) {
                    uint32_t ra;
                    asm("mapa.shared::cluster.u32 %0, %1, %2;"
                        : "=r"(ra) : "r"(dst), "r"(p));
                    asm volatile("st.shared::cluster.b64 [%0], %1;"
                                 :: "r"(ra), "l"(q0) : "memory");
                    asm volatile("st.shared::cluster.b64 [%0], %1;"
                                 :: "r"(ra + 8), "l"(q1) : "memory");
                }
                // prefetch gx for t+1 (overlaps with barrier wait)
                const float* gxr = gx + ((size_t)(t + 1) * B_SZ + b) * G_SZ;
                ir  = *(const float4*)(gxr + cb);
                iz  = *(const float4*)(gxr + 256 + cb);
                inn = *(const float4*)(gxr + 512 + cb);
            } else {
                *(float4*)(finals + (size_t)b * 256 + cb) = hv;
            }
        }

        if (t != T_LEN - 1) {
            asm volatile("barrier.cluster.arrive.aligned;" ::: "memory");
            asm volatile("barrier.cluster.wait.aligned;"   ::: "memory");
        }
    }
}

// ---------------------------------------------------------------------------
extern "C" void kernel_launch(void* const* d_in, const int* in_sizes, int n_in,
                              void* d_out, int out_size)
{
    const float* x     = (const float*)d_in[0];
    const float* h0    = (const float*)d_in[1];
    const float* Wih0  = (const float*)d_in[2];
    const float* Wih   = (const float*)d_in[3];
    const float* Whh   = (const float*)d_in[4];
    const float* bih   = (const float*)d_in[5];
    const float* bhh   = (const float*)d_in[6];
    float* out = (float*)d_out;

    float *gx_p = nullptr, *buf_p = nullptr;
    __nv_bfloat16 *ahi_p, *alo_p, *whi_p, *wlo_p;
    cudaGetSymbolAddress((void**)&gx_p,  g_gx);
    cudaGetSymbolAddress((void**)&buf_p, g_buf);
    cudaGetSymbolAddress((void**)&ahi_p, g_ahi);
    cudaGetSymbolAddress((void**)&alo_p, g_alo);
    cudaGetSymbolAddress((void**)&whi_p, g_whi);
    cudaGetSymbolAddress((void**)&wlo_p, g_wlo);

    cudaFuncSetAttribute(gru_scan_kernel,
                         cudaFuncAttributeMaxDynamicSharedMemorySize, SCAN_SMEM);
    cudaFuncSetAttribute(gemm_mma_kernel,
                         cudaFuncAttributeMaxDynamicSharedMemorySize, GSM_TOTAL);

    for (int l = 0; l < L_NUM; ++l) {
        const float* in  = (l == 0) ? x   : buf_p + (size_t)((l - 1) & 1) * TBH;
        float*       lo  = (l == L_NUM - 1) ? out : buf_p + (size_t)(l & 1) * TBH;
        const int    K   = (l == 0) ? I_SZ : H_SZ;
        const float* Wi  = (l == 0) ? Wih0 : Wih + (size_t)(l - 1) * G_SZ * H_SZ;
        const float* Wh  = Whh + (size_t)l * G_SZ * H_SZ;
        const float* bi  = bih + (size_t)l * G_SZ;
        const float* bh  = bhh + (size_t)l * G_SZ;

        int mk4 = M_ROWS * K / 4, wk4 = G_SZ * K / 4;
        conv_kernel<<<(mk4 + wk4 + 255) / 256, 256>>>(in, Wi, mk4, wk4);

        dim3 gg(G_SZ / 128, M_ROWS / 128);
        gemm_mma_kernel<<<gg, 256, GSM_TOTAL>>>(ahi_p, alo_p, whi_p, wlo_p,
                                                bi, gx_p, K);

        gru_scan_kernel<<<128, 256, SCAN_SMEM>>>(Wh, bh, gx_p,
                                                 h0 + (size_t)l * BH, lo,
                                                 out + TBH + (size_t)l * BH);
    }
}

// round 12
// speedup vs baseline: 1.5576x; 1.5355x over previous
#include <cuda_runtime.h>
#include <cuda_bf16.h>
#include <cstdint>

#define T_LEN 512
#define B_SZ  256
#define I_SZ  128
#define H_SZ  256
#define G_SZ  768
#define L_NUM 6

#define M_ROWS (T_LEN * B_SZ)                  // 131072
#define TBH    ((size_t)T_LEN * B_SZ * H_SZ)   // 33554432
#define BH     (B_SZ * H_SZ)                   // 65536

typedef unsigned long long ull;

// ------------------------------ scratch -----------------------------------
__device__ float g_gx[(size_t)M_ROWS * G_SZ];
__device__ float g_buf[2ULL * TBH];
__device__ __nv_bfloat16 g_ahi[(size_t)M_ROWS * 256];
__device__ __nv_bfloat16 g_alo[(size_t)M_ROWS * 256];
__device__ __nv_bfloat16 g_whi[G_SZ * 256];
__device__ __nv_bfloat16 g_wlo[G_SZ * 256];
__device__ __align__(128) ull g_bar2[16][16];

// ------------------------------ helpers -----------------------------------
__device__ __forceinline__ float tanh_f(float x) {
    float y; asm("tanh.approx.f32 %0, %1;" : "=f"(y) : "f"(x)); return y;
}
__device__ __forceinline__ float sigmf(float x) {
    return 0.5f * tanh_f(0.5f * x) + 0.5f;
}
__device__ __forceinline__ uint32_t smem_u32(const void* p) {
    uint32_t a;
    asm("{ .reg .u64 t; cvta.to.shared.u64 t, %1; cvt.u32.u64 %0, t; }"
        : "=r"(a) : "l"(p));
    return a;
}

// 8-CTA barrier per b-group (release arrive + acquire poll, monotonic ctr).
__device__ __forceinline__ void bg_barrier(int bg) {
    __syncthreads();
    if (threadIdx.x == 0) {
        ull* ctr = &g_bar2[bg][0];
        ull old;
        asm volatile("atom.release.gpu.global.add.u64 %0, [%1], 1;"
                     : "=l"(old) : "l"(ctr) : "memory");
        ull target = ((old + 1ULL + 7ULL) >> 3) << 3;
        if (old + 1ULL != target) {
            ull v;
            do {
                asm volatile("ld.acquire.gpu.global.u64 %0, [%1];"
                             : "=l"(v) : "l"(ctr) : "memory");
            } while (v < target);
        }
    }
    __syncthreads();
}

// ------------------------- fp32 -> bf16 hi/lo split -------------------------
__device__ __forceinline__ uint32_t bpack(float a, float b, bool lo) {
    __nv_bfloat16 ah = __float2bfloat16(a);
    __nv_bfloat16 bh = __float2bfloat16(b);
    if (lo) {
        ah = __float2bfloat16(a - __bfloat162float(ah));
        bh = __float2bfloat16(b - __bfloat162float(bh));
    }
    return (uint32_t)__bfloat16_as_ushort(ah) |
           ((uint32_t)__bfloat16_as_ushort(bh) << 16);
}

__global__ void conv_kernel(const float* __restrict__ A, const float* __restrict__ W,
                            int mk4, int wk4)
{
    int i = blockIdx.x * 256 + threadIdx.x;
    if (i < mk4) {
        float4 v = ((const float4*)A)[i];
        ((uint2*)g_ahi)[i] = make_uint2(bpack(v.x, v.y, false), bpack(v.z, v.w, false));
        ((uint2*)g_alo)[i] = make_uint2(bpack(v.x, v.y, true),  bpack(v.z, v.w, true));
    } else if (i < mk4 + wk4) {
        int j = i - mk4;
        float4 v = ((const float4*)W)[j];
        ((uint2*)g_whi)[j] = make_uint2(bpack(v.x, v.y, false), bpack(v.z, v.w, false));
        ((uint2*)g_wlo)[j] = make_uint2(bpack(v.x, v.y, true),  bpack(v.z, v.w, true));
    }
}

// ------------------------ mma primitives (proven) ---------------------------
__device__ __forceinline__ void ldmx4(uint32_t* r, uint32_t addr) {
    asm volatile("ldmatrix.sync.aligned.m8n8.x4.shared.b16 {%0,%1,%2,%3}, [%4];"
                 : "=r"(r[0]), "=r"(r[1]), "=r"(r[2]), "=r"(r[3]) : "r"(addr));
}
__device__ __forceinline__ void ldmx2(uint32_t* r, uint32_t addr) {
    asm volatile("ldmatrix.sync.aligned.m8n8.x2.shared.b16 {%0,%1}, [%2];"
                 : "=r"(r[0]), "=r"(r[1]) : "r"(addr));
}
__device__ __forceinline__ void mma16816(float* d, const uint32_t* a,
                                         uint32_t b0, uint32_t b1) {
    asm volatile(
        "mma.sync.aligned.m16n8k16.row.col.f32.bf16.bf16.f32 "
        "{%0,%1,%2,%3}, {%4,%5,%6,%7}, {%8,%9}, {%0,%1,%2,%3};"
        : "+f"(d[0]), "+f"(d[1]), "+f"(d[2]), "+f"(d[3])
        : "r"(a[0]), "r"(a[1]), "r"(a[2]), "r"(a[3]), "r"(b0), "r"(b1));
}

// ------------------------ mma.sync bf16 input GEMM (proven) -----------------
#define GROW 72
#define GTILE (128 * GROW * 2)
#define GSM_TOTAL (4 * GTILE)

__global__ void __launch_bounds__(256, 2)
gemm_mma_kernel(const __nv_bfloat16* __restrict__ Ahi,
                const __nv_bfloat16* __restrict__ Alo,
                const __nv_bfloat16* __restrict__ Whi,
                const __nv_bfloat16* __restrict__ Wlo,
                const float* __restrict__ bias,
                float* __restrict__ C, int K)
{
    extern __shared__ char gsm[];
    char* tAH = gsm;
    char* tAL = gsm + GTILE;
    char* tBH = gsm + 2 * GTILE;
    char* tBL = gsm + 3 * GTILE;

    const int tid = threadIdx.x;
    const int wid = tid >> 5;
    const int lane = tid & 31;
    const int wm = wid & 1;
    const int wn = wid >> 1;
    const int n0 = blockIdx.x * 128;
    const int m0 = blockIdx.y * 128;

    float acc[4][4][4];
    #pragma unroll
    for (int i = 0; i < 4; ++i)
        #pragma unroll
        for (int j = 0; j < 4; ++j)
            #pragma unroll
            for (int q = 0; q < 4; ++q) acc[i][j][q] = 0.0f;

    const int lrow = lane & 15;
    const int lkg  = (lane >> 4) * 8;

    const int nch = K >> 6;
    for (int c = 0; c < nch; ++c) {
        #pragma unroll
        for (int p = 0; p < 4; ++p) {
            int idx = p * 256 + tid;
            int row = idx >> 3;
            int k8  = (idx & 7) * 8;
            size_t ga = (size_t)(m0 + row) * K + c * 64 + k8;
            size_t gb = (size_t)(n0 + row) * K + c * 64 + k8;
            uint32_t so = (uint32_t)(row * (GROW * 2) + k8 * 2);
            *(uint4*)(tAH + so) = *(const uint4*)(Ahi + ga);
            *(uint4*)(tAL + so) = *(const uint4*)(Alo + ga);
            *(uint4*)(tBH + so) = *(const uint4*)(Whi + gb);
            *(uint4*)(tBL + so) = *(const uint4*)(Wlo + gb);
        }
        __syncthreads();

        #pragma unroll
        for (int pass = 0; pass < 3; ++pass) {
            const char* At = (pass == 2) ? tAL : tAH;
            const char* Bt = (pass == 1) ? tBL : tBH;
            const uint32_t abase = smem_u32(At) +
                (uint32_t)((wm * 64 + lrow) * (GROW * 2) + lkg * 2);
            const uint32_t bbase = smem_u32(Bt) +
                (uint32_t)((wn * 32 + lrow) * (GROW * 2) + lkg * 2);

            #pragma unroll
            for (int k16 = 0; k16 < 4; ++k16) {
                uint32_t a[4][4], b[2][4];
                #pragma unroll
                for (int mt = 0; mt < 4; ++mt)
                    ldmx4(a[mt], abase + mt * 16 * (GROW * 2) + k16 * 32);
                #pragma unroll
                for (int bh = 0; bh < 2; ++bh)
                    ldmx4(b[bh], bbase + bh * 16 * (GROW * 2) + k16 * 32);
                #pragma unroll
                for (int mt = 0; mt < 4; ++mt) {
                    #pragma unroll
                    for (int nt = 0; nt < 4; ++nt) {
                        int bh = nt >> 1, sub = nt & 1;
                        mma16816(acc[mt][nt], a[mt], b[bh][sub], b[bh][sub + 2]);
                    }
                }
            }
        }
        __syncthreads();
    }

    #pragma unroll
    for (int nt = 0; nt < 4; ++nt) {
        int col = n0 + wn * 32 + nt * 8 + (lane & 3) * 2;
        float2 bv = *(const float2*)(bias + col);
        #pragma unroll
        for (int mt = 0; mt < 4; ++mt) {
            int row = m0 + wm * 64 + mt * 16 + (lane >> 2);
            float2 o0 = { acc[mt][nt][0] + bv.x, acc[mt][nt][1] + bv.y };
            float2 o1 = { acc[mt][nt][2] + bv.x, acc[mt][nt][3] + bv.y };
            *(float2*)(C + (size_t)row * G_SZ + col) = o0;
            *(float2*)(C + (size_t)(row + 8) * G_SZ + col) = o1;
        }
    }
}

// ---------------------------------------------------------------------------
// Persistent recurrent scan on TENSOR CORES.
// 16 b-groups (16 rows) x 8 h-groups (32 h-cols -> 96 gate-cols = 12 n8-tiles).
// W_hh slice split hi/lo bf16 in smem (once); h staged+split per step.
// 3-pass hi/lo mma, fp32 acc; k-split 2 (warps 0-3: k16 0-7, warps 4-7: 8-15).
// Warp w handles tiles {w, w+4, w+8} = r/z/n gates of h-cols [w*8, w*8+8).
// ---------------------------------------------------------------------------
#define SROW  264                       // bf16 elems per row (k-pad)
#define SROWB (SROW * 2)                // 528 bytes
#define WS_E  (96 * SROW)               // W tile elems (per hi/lo)
#define AS_E  (16 * SROW)               // A (h) tile elems
#define HS_E  (16 * 260)                // fp32 h tile elems
#define SCAN_SMEM (2*WS_E*2 + 2*AS_E*2 + HS_E*4 + 128*12*4)   // 141056 B

__global__ void __launch_bounds__(256)
gru_scan_kernel(const float* __restrict__ Whh, const float* __restrict__ bhh,
                const float* __restrict__ gx, const float* __restrict__ hinit,
                float* __restrict__ out, float* __restrict__ finals)
{
    extern __shared__ char sm[];
    __nv_bfloat16* WSH = (__nv_bfloat16*)sm;          // [96][264]
    __nv_bfloat16* WSL = WSH + WS_E;
    __nv_bfloat16* ASH = WSL + WS_E;                  // [16][264]
    __nv_bfloat16* ASL = ASH + AS_E;
    float* hs  = (float*)(ASL + AS_E);                // [16][260]
    float* red = hs + HS_E;                           // [128][12]

    const int tid = threadIdx.x;
    const int bg = blockIdx.x >> 3;      // 0..15
    const int hg = blockIdx.x & 7;       // 0..7
    const int b0 = bg * 16;
    const int h0 = hg * 32;

    // Split W_hh slice into smem bf16 hi/lo: row j = gate-col (r:0-31,z:32-63,
    // n:64-95 of h-cols h0..h0+31), cols = k. Coalesced: iter n loads row n.
    for (int idx = tid; idx < 96 * 256; idx += 256) {
        int j = idx >> 8;
        int k = idx & 255;
        float v = Whh[(size_t)((j >> 5) * 256 + h0 + (j & 31)) * 256 + k];
        __nv_bfloat16 hb = __float2bfloat16(v);
        __nv_bfloat16 lb = __float2bfloat16(v - __bfloat162float(hb));
        WSH[j * SROW + k] = hb;
        WSL[j * SROW + k] = lb;
    }

    const int wid  = tid >> 5;
    const int L    = tid & 31;
    const int wmod = wid & 3;            // tile column group
    const int kb16 = (wid >> 2) * 8;     // k16 base (k-split)
    const int gr   = L >> 2;             // row 0..7 (and +8)
    const int ch   = h0 + wmod * 8 + (L & 3) * 2;   // global h-col pair base

    float2 brv = *(const float2*)(bhh + ch);
    float2 bzv = *(const float2*)(bhh + 256 + ch);
    float2 bnv = *(const float2*)(bhh + 512 + ch);

    // ldmatrix bases
    const uint32_t aH = smem_u32(ASH) +
        (uint32_t)((L & 15) * SROWB + (L >> 4) * 16);
    const uint32_t aL = aH + (uint32_t)(AS_E * 2);
    const uint32_t bH = smem_u32(WSH) +
        (uint32_t)((L & 7) * SROWB + ((L >> 3) & 1) * 16);
    const uint32_t bLo = bH + (uint32_t)(WS_E * 2);

    // gx prefetch for t=0 (finalizer warps 0-3)
    float2 pr0, pz0, pn0, pr1, pz1, pn1;
    if (wid < 4) {
        const float* q0 = gx + (size_t)(b0 + gr) * G_SZ + ch;
        const float* q1 = gx + (size_t)(b0 + gr + 8) * G_SZ + ch;
        pr0 = *(const float2*)(q0);       pr1 = *(const float2*)(q1);
        pz0 = *(const float2*)(q0 + 256); pz1 = *(const float2*)(q1 + 256);
        pn0 = *(const float2*)(q0 + 512); pn1 = *(const float2*)(q1 + 512);
    }

    __syncthreads();

    for (int t = 0; t < T_LEN; ++t) {
        // stage h_prev: global -> fp32 hs + bf16 hi/lo A tiles
        const float4* src4 = (t == 0)
            ? (const float4*)(hinit + (size_t)b0 * 256)
            : (const float4*)(out + ((size_t)(t - 1) * B_SZ + b0) * 256);
        #pragma unroll
        for (int p = 0; p < 4; ++p) {
            int f = tid + p * 256;           // 0..1023
            int row = f >> 6;
            int kq = f & 63;                 // float4 index in row
            float4 v = (t == 0) ? src4[row * 64 + kq]
                                : __ldcv(src4 + row * 64 + kq);
            *(float4*)(hs + row * 260 + kq * 4) = v;
            uint2 hiw, low;
            hiw.x = bpack(v.x, v.y, false); hiw.y = bpack(v.z, v.w, false);
            low.x = bpack(v.x, v.y, true);  low.y = bpack(v.z, v.w, true);
            *(uint2*)(ASH + row * SROW + kq * 4) = hiw;
            *(uint2*)(ASL + row * SROW + kq * 4) = low;
        }
        __syncthreads();

        float acc[3][4];
        #pragma unroll
        for (int q = 0; q < 3; ++q)
            #pragma unroll
            for (int i = 0; i < 4; ++i) acc[q][i] = 0.0f;

        #pragma unroll
        for (int pass = 0; pass < 3; ++pass) {
            uint32_t aB = (pass == 2) ? aL : aH;
            uint32_t bB = (pass == 1) ? bLo : bH;
            #pragma unroll
            for (int k16 = 0; k16 < 8; ++k16) {
                int kk = kb16 + k16;
                uint32_t a[4];
                ldmx4(a, aB + kk * 32);
                #pragma unroll
                for (int q = 0; q < 3; ++q) {
                    int nt = wmod + q * 4;
                    uint32_t bb[2];
                    ldmx2(bb, bB + nt * 8 * SROWB + kk * 32);
                    mma16816(acc[q], a, bb[0], bb[1]);
                }
            }
        }
        __syncthreads();

        // k-split reduce through smem
        if (wid >= 4) {
            float* rp = red + (tid & 127) * 12;
            #pragma unroll
            for (int q = 0; q < 3; ++q)
                #pragma unroll
                for (int i = 0; i < 4; ++i) rp[q * 4 + i] = acc[q][i];
        }
        __syncthreads();

        if (wid < 4) {
            const float* rp = red + tid * 12;
            #pragma unroll
            for (int q = 0; q < 3; ++q)
                #pragma unroll
                for (int i = 0; i < 4; ++i) acc[q][i] += rp[q * 4 + i];

            float2 hp0 = *(const float2*)(hs + gr * 260 + ch);
            float2 hp1 = *(const float2*)(hs + (gr + 8) * 260 + ch);

            // row gr
            float rg0 = sigmf(pr0.x + acc[0][0] + brv.x);
            float rg1 = sigmf(pr0.y + acc[0][1] + brv.y);
            float zg0 = sigmf(pz0.x + acc[1][0] + bzv.x);
            float zg1 = sigmf(pz0.y + acc[1][1] + bzv.y);
            float ng0 = tanh_f(pn0.x + rg0 * (acc[2][0] + bnv.x));
            float ng1 = tanh_f(pn0.y + rg1 * (acc[2][1] + bnv.y));
            float2 hv0 = { (1.0f - zg0) * ng0 + zg0 * hp0.x,
                           (1.0f - zg1) * ng1 + zg1 * hp0.y };
            // row gr+8
            float rg2 = sigmf(pr1.x + acc[0][2] + brv.x);
            float rg3 = sigmf(pr1.y + acc[0][3] + brv.y);
            float zg2 = sigmf(pz1.x + acc[1][2] + bzv.x);
            float zg3 = sigmf(pz1.y + acc[1][3] + bzv.y);
            float ng2 = tanh_f(pn1.x + rg2 * (acc[2][2] + bnv.x));
            float ng3 = tanh_f(pn1.y + rg3 * (acc[2][3] + bnv.y));
            float2 hv1 = { (1.0f - zg2) * ng2 + zg2 * hp1.x,
                           (1.0f - zg3) * ng3 + zg3 * hp1.y };

            *(float2*)(out + ((size_t)t * B_SZ + b0 + gr) * 256 + ch) = hv0;
            *(float2*)(out + ((size_t)t * B_SZ + b0 + gr + 8) * 256 + ch) = hv1;

            if (t == T_LEN - 1) {
                *(float2*)(finals + (size_t)(b0 + gr) * 256 + ch) = hv0;
                *(float2*)(finals + (size_t)(b0 + gr + 8) * 256 + ch) = hv1;
            } else {
                // prefetch gx for t+1 (hidden under barrier wait)
                const float* q0 = gx + ((size_t)(t + 1) * B_SZ + b0 + gr) * G_SZ + ch;
                const float* q1 = gx + ((size_t)(t + 1) * B_SZ + b0 + gr + 8) * G_SZ + ch;
                pr0 = *(const float2*)(q0);       pr1 = *(const float2*)(q1);
                pz0 = *(const float2*)(q0 + 256); pz1 = *(const float2*)(q1 + 256);
                pn0 = *(const float2*)(q0 + 512); pn1 = *(const float2*)(q1 + 512);
            }
        }

        if (t != T_LEN - 1) bg_barrier(bg);
        else __syncthreads();
    }
}

// ---------------------------------------------------------------------------
extern "C" void kernel_launch(void* const* d_in, const int* in_sizes, int n_in,
                              void* d_out, int out_size)
{
    const float* x     = (const float*)d_in[0];
    const float* h0    = (const float*)d_in[1];
    const float* Wih0  = (const float*)d_in[2];
    const float* Wih   = (const float*)d_in[3];
    const float* Whh   = (const float*)d_in[4];
    const float* bih   = (const float*)d_in[5];
    const float* bhh   = (const float*)d_in[6];
    float* out = (float*)d_out;

    float *gx_p = nullptr, *buf_p = nullptr;
    __nv_bfloat16 *ahi_p, *alo_p, *whi_p, *wlo_p;
    cudaGetSymbolAddress((void**)&gx_p,  g_gx);
    cudaGetSymbolAddress((void**)&buf_p, g_buf);
    cudaGetSymbolAddress((void**)&ahi_p, g_ahi);
    cudaGetSymbolAddress((void**)&alo_p, g_alo);
    cudaGetSymbolAddress((void**)&whi_p, g_whi);
    cudaGetSymbolAddress((void**)&wlo_p, g_wlo);

    cudaFuncSetAttribute(gru_scan_kernel,
                         cudaFuncAttributeMaxDynamicSharedMemorySize, SCAN_SMEM);
    cudaFuncSetAttribute(gemm_mma_kernel,
                         cudaFuncAttributeMaxDynamicSharedMemorySize, GSM_TOTAL);

    for (int l = 0; l < L_NUM; ++l) {
        const float* in  = (l == 0) ? x   : buf_p + (size_t)((l - 1) & 1) * TBH;
        float*       lo  = (l == L_NUM - 1) ? out : buf_p + (size_t)(l & 1) * TBH;
        const int    K   = (l == 0) ? I_SZ : H_SZ;
        const float* Wi  = (l == 0) ? Wih0 : Wih + (size_t)(l - 1) * G_SZ * H_SZ;
        const float* Wh  = Whh + (size_t)l * G_SZ * H_SZ;
        const float* bi  = bih + (size_t)l * G_SZ;
        const float* bh  = bhh + (size_t)l * G_SZ;

        int mk4 = M_ROWS * K / 4, wk4 = G_SZ * K / 4;
        conv_kernel<<<(mk4 + wk4 + 255) / 256, 256>>>(in, Wi, mk4, wk4);

        dim3 gg(G_SZ / 128, M_ROWS / 128);
        gemm_mma_kernel<<<gg, 256, GSM_TOTAL>>>(ahi_p, alo_p, whi_p, wlo_p,
                                                bi, gx_p, K);

        gru_scan_kernel<<<128, 256, SCAN_SMEM>>>(Wh, bh, gx_p,
                                                 h0 + (size_t)l * BH, lo,
                                                 out + TBH + (size_t)l * BH);
    }
}

// round 13
// speedup vs baseline: 1.7031x; 1.0934x over previous
#include <cuda_runtime.h>
#include <cuda_bf16.h>
#include <cstdint>

#define T_LEN 512
#define B_SZ  256
#define I_SZ  128
#define H_SZ  256
#define G_SZ  768
#define L_NUM 6

#define M_ROWS (T_LEN * B_SZ)                  // 131072
#define TBH    ((size_t)T_LEN * B_SZ * H_SZ)   // 33554432
#define BH     (B_SZ * H_SZ)                   // 65536

typedef unsigned long long ull;

// ------------------------------ scratch -----------------------------------
__device__ float g_gx[(size_t)M_ROWS * G_SZ];
__device__ float g_buf[2ULL * TBH];
__device__ __nv_bfloat16 g_ahi[(size_t)M_ROWS * 256];
__device__ __nv_bfloat16 g_alo[(size_t)M_ROWS * 256];
__device__ __nv_bfloat16 g_whi[G_SZ * 256];
__device__ __nv_bfloat16 g_wlo[G_SZ * 256];
__device__ __nv_bfloat16 g_hex[2][B_SZ][512];   // [parity][row][hi256|lo256]
__device__ __align__(128) ull g_bar2[16][16];

// ------------------------------ helpers -----------------------------------
__device__ __forceinline__ float tanh_f(float x) {
    float y; asm("tanh.approx.f32 %0, %1;" : "=f"(y) : "f"(x)); return y;
}
__device__ __forceinline__ float sigmf(float x) {
    return 0.5f * tanh_f(0.5f * x) + 0.5f;
}
__device__ __forceinline__ uint32_t smem_u32(const void* p) {
    uint32_t a;
    asm("{ .reg .u64 t; cvta.to.shared.u64 t, %1; cvt.u32.u64 %0, t; }"
        : "=r"(a) : "l"(p));
    return a;
}

// 8-CTA barrier per b-group (release arrive + acquire poll, monotonic ctr).
__device__ __forceinline__ void bg_barrier(int bg) {
    __syncthreads();
    if (threadIdx.x == 0) {
        ull* ctr = &g_bar2[bg][0];
        ull old;
        asm volatile("atom.release.gpu.global.add.u64 %0, [%1], 1;"
                     : "=l"(old) : "l"(ctr) : "memory");
        ull target = ((old + 1ULL + 7ULL) >> 3) << 3;
        if (old + 1ULL != target) {
            ull v;
            do {
                asm volatile("ld.acquire.gpu.global.u64 %0, [%1];"
                             : "=l"(v) : "l"(ctr) : "memory");
            } while (v < target);
        }
    }
    __syncthreads();
}

// ------------------------- fp32 -> bf16 hi/lo split -------------------------
__device__ __forceinline__ uint32_t bpack(float a, float b, bool lo) {
    __nv_bfloat16 ah = __float2bfloat16(a);
    __nv_bfloat16 bh = __float2bfloat16(b);
    if (lo) {
        ah = __float2bfloat16(a - __bfloat162float(ah));
        bh = __float2bfloat16(b - __bfloat162float(bh));
    }
    return (uint32_t)__bfloat16_as_ushort(ah) |
           ((uint32_t)__bfloat16_as_ushort(bh) << 16);
}

__global__ void conv_kernel(const float* __restrict__ A, const float* __restrict__ W,
                            int mk4, int wk4)
{
    int i = blockIdx.x * 256 + threadIdx.x;
    if (i < mk4) {
        float4 v = ((const float4*)A)[i];
        ((uint2*)g_ahi)[i] = make_uint2(bpack(v.x, v.y, false), bpack(v.z, v.w, false));
        ((uint2*)g_alo)[i] = make_uint2(bpack(v.x, v.y, true),  bpack(v.z, v.w, true));
    } else if (i < mk4 + wk4) {
        int j = i - mk4;
        float4 v = ((const float4*)W)[j];
        ((uint2*)g_whi)[j] = make_uint2(bpack(v.x, v.y, false), bpack(v.z, v.w, false));
        ((uint2*)g_wlo)[j] = make_uint2(bpack(v.x, v.y, true),  bpack(v.z, v.w, true));
    }
}

// ------------------------ mma primitives (proven) ---------------------------
__device__ __forceinline__ void ldmx4(uint32_t* r, uint32_t addr) {
    asm volatile("ldmatrix.sync.aligned.m8n8.x4.shared.b16 {%0,%1,%2,%3}, [%4];"
                 : "=r"(r[0]), "=r"(r[1]), "=r"(r[2]), "=r"(r[3]) : "r"(addr));
}
__device__ __forceinline__ void ldmx2(uint32_t* r, uint32_t addr) {
    asm volatile("ldmatrix.sync.aligned.m8n8.x2.shared.b16 {%0,%1}, [%2];"
                 : "=r"(r[0]), "=r"(r[1]) : "r"(addr));
}
__device__ __forceinline__ void mma16816(float* d, const uint32_t* a,
                                         uint32_t b0, uint32_t b1) {
    asm volatile(
        "mma.sync.aligned.m16n8k16.row.col.f32.bf16.bf16.f32 "
        "{%0,%1,%2,%3}, {%4,%5,%6,%7}, {%8,%9}, {%0,%1,%2,%3};"
        : "+f"(d[0]), "+f"(d[1]), "+f"(d[2]), "+f"(d[3])
        : "r"(a[0]), "r"(a[1]), "r"(a[2]), "r"(a[3]), "r"(b0), "r"(b1));
}

// ------------------------ mma.sync bf16 input GEMM (proven) -----------------
#define GROW 72
#define GTILE (128 * GROW * 2)
#define GSM_TOTAL (4 * GTILE)

__global__ void __launch_bounds__(256, 2)
gemm_mma_kernel(const __nv_bfloat16* __restrict__ Ahi,
                const __nv_bfloat16* __restrict__ Alo,
                const __nv_bfloat16* __restrict__ Whi,
                const __nv_bfloat16* __restrict__ Wlo,
                const float* __restrict__ bias,
                float* __restrict__ C, int K)
{
    extern __shared__ char gsm[];
    char* tAH = gsm;
    char* tAL = gsm + GTILE;
    char* tBH = gsm + 2 * GTILE;
    char* tBL = gsm + 3 * GTILE;

    const int tid = threadIdx.x;
    const int wid = tid >> 5;
    const int lane = tid & 31;
    const int wm = wid & 1;
    const int wn = wid >> 1;
    const int n0 = blockIdx.x * 128;
    const int m0 = blockIdx.y * 128;

    float acc[4][4][4];
    #pragma unroll
    for (int i = 0; i < 4; ++i)
        #pragma unroll
        for (int j = 0; j < 4; ++j)
            #pragma unroll
            for (int q = 0; q < 4; ++q) acc[i][j][q] = 0.0f;

    const int lrow = lane & 15;
    const int lkg  = (lane >> 4) * 8;

    const int nch = K >> 6;
    for (int c = 0; c < nch; ++c) {
        #pragma unroll
        for (int p = 0; p < 4; ++p) {
            int idx = p * 256 + tid;
            int row = idx >> 3;
            int k8  = (idx & 7) * 8;
            size_t ga = (size_t)(m0 + row) * K + c * 64 + k8;
            size_t gb = (size_t)(n0 + row) * K + c * 64 + k8;
            uint32_t so = (uint32_t)(row * (GROW * 2) + k8 * 2);
            *(uint4*)(tAH + so) = *(const uint4*)(Ahi + ga);
            *(uint4*)(tAL + so) = *(const uint4*)(Alo + ga);
            *(uint4*)(tBH + so) = *(const uint4*)(Whi + gb);
            *(uint4*)(tBL + so) = *(const uint4*)(Wlo + gb);
        }
        __syncthreads();

        #pragma unroll
        for (int pass = 0; pass < 3; ++pass) {
            const char* At = (pass == 2) ? tAL : tAH;
            const char* Bt = (pass == 1) ? tBL : tBH;
            const uint32_t abase = smem_u32(At) +
                (uint32_t)((wm * 64 + lrow) * (GROW * 2) + lkg * 2);
            const uint32_t bbase = smem_u32(Bt) +
                (uint32_t)((wn * 32 + lrow) * (GROW * 2) + lkg * 2);

            #pragma unroll
            for (int k16 = 0; k16 < 4; ++k16) {
                uint32_t a[4][4], b[2][4];
                #pragma unroll
                for (int mt = 0; mt < 4; ++mt)
                    ldmx4(a[mt], abase + mt * 16 * (GROW * 2) + k16 * 32);
                #pragma unroll
                for (int bh = 0; bh < 2; ++bh)
                    ldmx4(b[bh], bbase + bh * 16 * (GROW * 2) + k16 * 32);
                #pragma unroll
                for (int mt = 0; mt < 4; ++mt) {
                    #pragma unroll
                    for (int nt = 0; nt < 4; ++nt) {
                        int bh = nt >> 1, sub = nt & 1;
                        mma16816(acc[mt][nt], a[mt], b[bh][sub], b[bh][sub + 2]);
                    }
                }
            }
        }
        __syncthreads();
    }

    #pragma unroll
    for (int nt = 0; nt < 4; ++nt) {
        int col = n0 + wn * 32 + nt * 8 + (lane & 3) * 2;
        float2 bv = *(const float2*)(bias + col);
        #pragma unroll
        for (int mt = 0; mt < 4; ++mt) {
            int row = m0 + wm * 64 + mt * 16 + (lane >> 2);
            float2 o0 = { acc[mt][nt][0] + bv.x, acc[mt][nt][1] + bv.y };
            float2 o1 = { acc[mt][nt][2] + bv.x, acc[mt][nt][3] + bv.y };
            *(float2*)(C + (size_t)row * G_SZ + col) = o0;
            *(float2*)(C + (size_t)(row + 8) * G_SZ + col) = o1;
        }
    }
}

// ---------------------------------------------------------------------------
// Persistent recurrent scan on tensor cores, v2:
//  - W fragments hoisted into registers (zero W smem traffic per step)
//  - hp carried in registers (thread ownership is time-invariant)
//  - h exchanged as pre-split bf16 hi/lo via g_hex (parity double buffer)
// 16 b-groups x 8 h-groups; 256 threads; k-split 2 across warp halves.
// ---------------------------------------------------------------------------
#define SROW  264
#define SROWB (SROW * 2)
#define WS_E  (96 * SROW)
#define AS_E  (16 * SROW)
#define SCAN_SMEM (2*WS_E*2 + 2*AS_E*2 + 128*12*4)   // 124416 B

__global__ void __launch_bounds__(256)
gru_scan_kernel(const float* __restrict__ Whh, const float* __restrict__ bhh,
                const float* __restrict__ gx, const float* __restrict__ hinit,
                float* __restrict__ out, float* __restrict__ finals)
{
    extern __shared__ char sm[];
    __nv_bfloat16* WSH = (__nv_bfloat16*)sm;          // [96][264]
    __nv_bfloat16* WSL = WSH + WS_E;
    __nv_bfloat16* ASH = WSL + WS_E;                  // [16][264]
    __nv_bfloat16* ASL = ASH + AS_E;
    float* red = (float*)(ASL + AS_E);                // [128][12]

    const int tid = threadIdx.x;
    const int bg = blockIdx.x >> 3;      // 0..15
    const int hg = blockIdx.x & 7;       // 0..7
    const int b0 = bg * 16;
    const int h0 = hg * 32;

    // Split W_hh slice into smem bf16 hi/lo (used once to build fragments).
    for (int idx = tid; idx < 96 * 256; idx += 256) {
        int j = idx >> 8;
        int k = idx & 255;
        float v = Whh[(size_t)((j >> 5) * 256 + h0 + (j & 31)) * 256 + k];
        __nv_bfloat16 hb = __float2bfloat16(v);
        __nv_bfloat16 lb = __float2bfloat16(v - __bfloat162float(hb));
        WSH[j * SROW + k] = hb;
        WSL[j * SROW + k] = lb;
    }

    const int wid  = tid >> 5;
    const int L    = tid & 31;
    const int wmod = wid & 3;            // tile column group
    const int kb16 = (wid >> 2) * 8;     // k16 base (k-split)
    const int gr   = L >> 2;             // row 0..7 (and +8)
    const int ch   = h0 + wmod * 8 + (L & 3) * 2;

    float2 brv = *(const float2*)(bhh + ch);
    float2 bzv = *(const float2*)(bhh + 256 + ch);
    float2 bnv = *(const float2*)(bhh + 512 + ch);

    const uint32_t aH = smem_u32(ASH) +
        (uint32_t)((L & 15) * SROWB + (L >> 4) * 16);
    const uint32_t aL = aH + (uint32_t)(AS_E * 2);
    const uint32_t bHb = smem_u32(WSH) +
        (uint32_t)((L & 7) * SROWB + ((L >> 3) & 1) * 16);
    const uint32_t bLb = bHb + (uint32_t)(WS_E * 2);

    // stage h(t=0) from hinit (fp32 -> bf16 hi/lo tiles)
    {
        const float4* src4 = (const float4*)(hinit + (size_t)b0 * 256);
        #pragma unroll
        for (int p = 0; p < 4; ++p) {
            int f = tid + p * 256;
            int row = f >> 6;
            int kq = f & 63;
            float4 v = src4[row * 64 + kq];
            uint2 hiw, low;
            hiw.x = bpack(v.x, v.y, false); hiw.y = bpack(v.z, v.w, false);
            low.x = bpack(v.x, v.y, true);  low.y = bpack(v.z, v.w, true);
            *(uint2*)(ASH + row * SROW + kq * 4) = hiw;
            *(uint2*)(ASL + row * SROW + kq * 4) = low;
        }
    }

    // hp registers (finalizers) + gx prefetch for t=0
    float2 hp0, hp1, pr0, pz0, pn0, pr1, pz1, pn1;
    if (wid < 4) {
        hp0 = *(const float2*)(hinit + (size_t)(b0 + gr) * 256 + ch);
        hp1 = *(const float2*)(hinit + (size_t)(b0 + gr + 8) * 256 + ch);
        const float* q0 = gx + (size_t)(b0 + gr) * G_SZ + ch;
        const float* q1 = gx + (size_t)(b0 + gr + 8) * G_SZ + ch;
        pr0 = *(const float2*)(q0);       pr1 = *(const float2*)(q1);
        pz0 = *(const float2*)(q0 + 256); pz1 = *(const float2*)(q1 + 256);
        pn0 = *(const float2*)(q0 + 512); pn1 = *(const float2*)(q1 + 512);
    }

    __syncthreads();

    // Hoist W fragments into registers: Bf0 = W_hi, Bf1 = W_lo.
    uint32_t Bf0[3][8][2], Bf1[3][8][2];
    #pragma unroll
    for (int q = 0; q < 3; ++q) {
        const uint32_t nofs = (uint32_t)((wmod + q * 4) * 8 * SROWB);
        #pragma unroll
        for (int k16 = 0; k16 < 8; ++k16) {
            ldmx2(Bf0[q][k16], bHb + nofs + (kb16 + k16) * 32);
            ldmx2(Bf1[q][k16], bLb + nofs + (kb16 + k16) * 32);
        }
    }

    for (int t = 0; t < T_LEN; ++t) {
        if (t > 0) {
            // stage h(t-1): bf16 hi/lo straight copy from g_hex[t&1]
            const uint4* src = (const uint4*)(&g_hex[t & 1][b0][0]);
            #pragma unroll
            for (int p = 0; p < 4; ++p) {
                int f = tid + p * 256;            // 0..1023
                int row = f >> 6;
                int q = f & 63;                   // uint4 within 1024B row
                uint4 v = __ldcv(src + row * 64 + q);
                __nv_bfloat16* dst = (q < 32)
                    ? (ASH + row * SROW + q * 8)
                    : (ASL + row * SROW + (q - 32) * 8);
                *(uint4*)dst = v;
            }
            __syncthreads();
        }

        float acc[3][4];
        #pragma unroll
        for (int q = 0; q < 3; ++q)
            #pragma unroll
            for (int i = 0; i < 4; ++i) acc[q][i] = 0.0f;

        #pragma unroll
        for (int pass = 0; pass < 3; ++pass) {
            uint32_t aB = (pass == 2) ? aL : aH;
            #pragma unroll
            for (int k16 = 0; k16 < 8; ++k16) {
                uint32_t a[4];
                ldmx4(a, aB + (kb16 + k16) * 32);
                #pragma unroll
                for (int q = 0; q < 3; ++q) {
                    if (pass == 1) mma16816(acc[q], a, Bf1[q][k16][0], Bf1[q][k16][1]);
                    else           mma16816(acc[q], a, Bf0[q][k16][0], Bf0[q][k16][1]);
                }
            }
        }
        __syncthreads();

        if (wid >= 4) {
            float* rp = red + (tid & 127) * 12;
            #pragma unroll
            for (int q = 0; q < 3; ++q)
                #pragma unroll
                for (int i = 0; i < 4; ++i) rp[q * 4 + i] = acc[q][i];
        }
        __syncthreads();

        if (wid < 4) {
            const float* rp = red + tid * 12;
            #pragma unroll
            for (int q = 0; q < 3; ++q)
                #pragma unroll
                for (int i = 0; i < 4; ++i) acc[q][i] += rp[q * 4 + i];

            float rg0 = sigmf(pr0.x + acc[0][0] + brv.x);
            float rg1 = sigmf(pr0.y + acc[0][1] + brv.y);
            float zg0 = sigmf(pz0.x + acc[1][0] + bzv.x);
            float zg1 = sigmf(pz0.y + acc[1][1] + bzv.y);
            float ng0 = tanh_f(pn0.x + rg0 * (acc[2][0] + bnv.x));
            float ng1 = tanh_f(pn0.y + rg1 * (acc[2][1] + bnv.y));
            float2 hv0 = { (1.0f - zg0) * ng0 + zg0 * hp0.x,
                           (1.0f - zg1) * ng1 + zg1 * hp0.y };
            float rg2 = sigmf(pr1.x + acc[0][2] + brv.x);
            float rg3 = sigmf(pr1.y + acc[0][3] + brv.y);
            float zg2 = sigmf(pz1.x + acc[1][2] + bzv.x);
            float zg3 = sigmf(pz1.y + acc[1][3] + bzv.y);
            float ng2 = tanh_f(pn1.x + rg2 * (acc[2][2] + bnv.x));
            float ng3 = tanh_f(pn1.y + rg3 * (acc[2][3] + bnv.y));
            float2 hv1 = { (1.0f - zg2) * ng2 + zg2 * hp1.x,
                           (1.0f - zg3) * ng3 + zg3 * hp1.y };

            hp0 = hv0; hp1 = hv1;

            *(float2*)(out + ((size_t)t * B_SZ + b0 + gr) * 256 + ch) = hv0;
            *(float2*)(out + ((size_t)t * B_SZ + b0 + gr + 8) * 256 + ch) = hv1;

            if (t == T_LEN - 1) {
                *(float2*)(finals + (size_t)(b0 + gr) * 256 + ch) = hv0;
                *(float2*)(finals + (size_t)(b0 + gr + 8) * 256 + ch) = hv1;
            } else {
                // exchange: pre-split bf16 hi/lo into parity buffer
                int par = (t + 1) & 1;
                __nv_bfloat16* e0 = &g_hex[par][b0 + gr][0];
                __nv_bfloat16* e1 = &g_hex[par][b0 + gr + 8][0];
                *(uint32_t*)(e0 + ch)       = bpack(hv0.x, hv0.y, false);
                *(uint32_t*)(e0 + 256 + ch) = bpack(hv0.x, hv0.y, true);
                *(uint32_t*)(e1 + ch)       = bpack(hv1.x, hv1.y, false);
                *(uint32_t*)(e1 + 256 + ch) = bpack(hv1.x, hv1.y, true);

                // prefetch gx for t+1 (hidden under barrier wait)
                const float* q0 = gx + ((size_t)(t + 1) * B_SZ + b0 + gr) * G_SZ + ch;
                const float* q1 = gx + ((size_t)(t + 1) * B_SZ + b0 + gr + 8) * G_SZ + ch;
                pr0 = *(const float2*)(q0);       pr1 = *(const float2*)(q1);
                pz0 = *(const float2*)(q0 + 256); pz1 = *(const float2*)(q1 + 256);
                pn0 = *(const float2*)(q0 + 512); pn1 = *(const float2*)(q1 + 512);
            }
        }

        if (t != T_LEN - 1) bg_barrier(bg);
    }
}

// ---------------------------------------------------------------------------
extern "C" void kernel_launch(void* const* d_in, const int* in_sizes, int n_in,
                              void* d_out, int out_size)
{
    const float* x     = (const float*)d_in[0];
    const float* h0    = (const float*)d_in[1];
    const float* Wih0  = (const float*)d_in[2];
    const float* Wih   = (const float*)d_in[3];
    const float* Whh   = (const float*)d_in[4];
    const float* bih   = (const float*)d_in[5];
    const float* bhh   = (const float*)d_in[6];
    float* out = (float*)d_out;

    float *gx_p = nullptr, *buf_p = nullptr;
    __nv_bfloat16 *ahi_p, *alo_p, *whi_p, *wlo_p;
    cudaGetSymbolAddress((void**)&gx_p,  g_gx);
    cudaGetSymbolAddress((void**)&buf_p, g_buf);
    cudaGetSymbolAddress((void**)&ahi_p, g_ahi);
    cudaGetSymbolAddress((void**)&alo_p, g_alo);
    cudaGetSymbolAddress((void**)&whi_p, g_whi);
    cudaGetSymbolAddress((void**)&wlo_p, g_wlo);

    cudaFuncSetAttribute(gru_scan_kernel,
                         cudaFuncAttributeMaxDynamicSharedMemorySize, SCAN_SMEM);
    cudaFuncSetAttribute(gemm_mma_kernel,
                         cudaFuncAttributeMaxDynamicSharedMemorySize, GSM_TOTAL);

    for (int l = 0; l < L_NUM; ++l) {
        const float* in  = (l == 0) ? x   : buf_p + (size_t)((l - 1) & 1) * TBH;
        float*       lo  = (l == L_NUM - 1) ? out : buf_p + (size_t)(l & 1) * TBH;
        const int    K   = (l == 0) ? I_SZ : H_SZ;
        const float* Wi  = (l == 0) ? Wih0 : Wih + (size_t)(l - 1) * G_SZ * H_SZ;
        const float* Wh  = Whh + (size_t)l * G_SZ * H_SZ;
        const float* bi  = bih + (size_t)l * G_SZ;
        const float* bh  = bhh + (size_t)l * G_SZ;

        int mk4 = M_ROWS * K / 4, wk4 = G_SZ * K / 4;
        conv_kernel<<<(mk4 + wk4 + 255) / 256, 256>>>(in, Wi, mk4, wk4);

        dim3 gg(G_SZ / 128, M_ROWS / 128);
        gemm_mma_kernel<<<gg, 256, GSM_TOTAL>>>(ahi_p, alo_p, whi_p, wlo_p,
                                                bi, gx_p, K);

        gru_scan_kernel<<<128, 256, SCAN_SMEM>>>(Wh, bh, gx_p,
                                                 h0 + (size_t)l * BH, lo,
                                                 out + TBH + (size_t)l * BH);
    }
}

// round 14
// speedup vs baseline: 1.7548x; 1.0304x over previous
#include <cuda_runtime.h>
#include <cuda_bf16.h>
#include <cstdint>

#define T_LEN 512
#define B_SZ  256
#define I_SZ  128
#define H_SZ  256
#define G_SZ  768
#define L_NUM 6

#define M_ROWS (T_LEN * B_SZ)                  // 131072
#define TBH    ((size_t)T_LEN * B_SZ * H_SZ)   // 33554432
#define BH     (B_SZ * H_SZ)                   // 65536

typedef unsigned long long ull;

// ------------------------------ scratch -----------------------------------
__device__ float g_gx[(size_t)M_ROWS * G_SZ];
__device__ float g_buf[2ULL * TBH];
__device__ __nv_bfloat16 g_ahi[(size_t)M_ROWS * 256];
__device__ __nv_bfloat16 g_alo[(size_t)M_ROWS * 256];
__device__ __nv_bfloat16 g_whi[G_SZ * 256];
__device__ __nv_bfloat16 g_wlo[G_SZ * 256];
__device__ __nv_bfloat16 g_hex[2][B_SZ][512];   // [parity][row][hi256|lo256]
__device__ __align__(128) ull g_bar2[16][16];

// ------------------------------ helpers -----------------------------------
__device__ __forceinline__ float tanh_f(float x) {
    float y; asm("tanh.approx.f32 %0, %1;" : "=f"(y) : "f"(x)); return y;
}
__device__ __forceinline__ float sigmf(float x) {
    return 0.5f * tanh_f(0.5f * x) + 0.5f;
}
__device__ __forceinline__ uint32_t smem_u32(const void* p) {
    uint32_t a;
    asm("{ .reg .u64 t; cvta.to.shared.u64 t, %1; cvt.u32.u64 %0, t; }"
        : "=r"(a) : "l"(p));
    return a;
}

// 8-CTA barrier per b-group (release arrive + acquire poll, monotonic ctr).
__device__ __forceinline__ void bg_barrier(int bg) {
    __syncthreads();
    if (threadIdx.x == 0) {
        ull* ctr = &g_bar2[bg][0];
        ull old;
        asm volatile("atom.release.gpu.global.add.u64 %0, [%1], 1;"
                     : "=l"(old) : "l"(ctr) : "memory");
        ull target = ((old + 1ULL + 7ULL) >> 3) << 3;
        if (old + 1ULL != target) {
            ull v;
            do {
                asm volatile("ld.acquire.gpu.global.u64 %0, [%1];"
                             : "=l"(v) : "l"(ctr) : "memory");
            } while (v < target);
        }
    }
    __syncthreads();
}

// ------------------------- fp32 -> bf16 hi/lo split -------------------------
__device__ __forceinline__ uint32_t bpack(float a, float b, bool lo) {
    __nv_bfloat16 ah = __float2bfloat16(a);
    __nv_bfloat16 bh = __float2bfloat16(b);
    if (lo) {
        ah = __float2bfloat16(a - __bfloat162float(ah));
        bh = __float2bfloat16(b - __bfloat162float(bh));
    }
    return (uint32_t)__bfloat16_as_ushort(ah) |
           ((uint32_t)__bfloat16_as_ushort(bh) << 16);
}

__global__ void conv_kernel(const float* __restrict__ A, const float* __restrict__ W,
                            int mk4, int wk4)
{
    int i = blockIdx.x * 256 + threadIdx.x;
    if (i < mk4) {
        float4 v = ((const float4*)A)[i];
        ((uint2*)g_ahi)[i] = make_uint2(bpack(v.x, v.y, false), bpack(v.z, v.w, false));
        ((uint2*)g_alo)[i] = make_uint2(bpack(v.x, v.y, true),  bpack(v.z, v.w, true));
    } else if (i < mk4 + wk4) {
        int j = i - mk4;
        float4 v = ((const float4*)W)[j];
        ((uint2*)g_whi)[j] = make_uint2(bpack(v.x, v.y, false), bpack(v.z, v.w, false));
        ((uint2*)g_wlo)[j] = make_uint2(bpack(v.x, v.y, true),  bpack(v.z, v.w, true));
    }
}

// ------------------------ mma primitives (proven) ---------------------------
__device__ __forceinline__ void ldmx4(uint32_t* r, uint32_t addr) {
    asm volatile("ldmatrix.sync.aligned.m8n8.x4.shared.b16 {%0,%1,%2,%3}, [%4];"
                 : "=r"(r[0]), "=r"(r[1]), "=r"(r[2]), "=r"(r[3]) : "r"(addr));
}
__device__ __forceinline__ void ldmx2(uint32_t* r, uint32_t addr) {
    asm volatile("ldmatrix.sync.aligned.m8n8.x2.shared.b16 {%0,%1}, [%2];"
                 : "=r"(r[0]), "=r"(r[1]) : "r"(addr));
}
__device__ __forceinline__ void mma16816(float* d, const uint32_t* a,
                                         uint32_t b0, uint32_t b1) {
    asm volatile(
        "mma.sync.aligned.m16n8k16.row.col.f32.bf16.bf16.f32 "
        "{%0,%1,%2,%3}, {%4,%5,%6,%7}, {%8,%9}, {%0,%1,%2,%3};"
        : "+f"(d[0]), "+f"(d[1]), "+f"(d[2]), "+f"(d[3])
        : "r"(a[0]), "r"(a[1]), "r"(a[2]), "r"(a[3]), "r"(b0), "r"(b1));
}
__device__ __forceinline__ void cpasync16(uint32_t saddr, const void* g) {
    asm volatile("cp.async.ca.shared.global [%0], [%1], 16;"
                 :: "r"(saddr), "l"(g) : "memory");
}

// ------------------------ mma.sync bf16 input GEMM v2 ----------------------
// cp.async 2-stage pipeline, k-chunk 32, 40-bf16 padded rows, 2 CTAs/SM.
#define SR2  40
#define SR2B 80
#define T2   (128 * SR2B)               // 10240 B per tile
#define STAGE2 (4 * T2)                 // 40960 B per stage
#define GSM2 (2 * STAGE2)               // 81920 B

__global__ void __launch_bounds__(256, 2)
gemm_mma_kernel(const __nv_bfloat16* __restrict__ Ahi,
                const __nv_bfloat16* __restrict__ Alo,
                const __nv_bfloat16* __restrict__ Whi,
                const __nv_bfloat16* __restrict__ Wlo,
                const float* __restrict__ bias,
                float* __restrict__ C, int K)
{
    extern __shared__ char gsm[];
    const uint32_t sbase = smem_u32(gsm);

    const int tid = threadIdx.x;
    const int wid = tid >> 5;
    const int lane = tid & 31;
    const int wm = wid & 1;
    const int wn = wid >> 1;
    const int n0 = blockIdx.x * 128;
    const int m0 = blockIdx.y * 128;

    const int srow = tid >> 2;           // staging: rows 0..63 (x4 per p)
    const int sq   = tid & 3;            // 16B chunk within 64B row

    float acc[4][4][4];
    #pragma unroll
    for (int i = 0; i < 4; ++i)
        #pragma unroll
        for (int j = 0; j < 4; ++j)
            #pragma unroll
            for (int q = 0; q < 4; ++q) acc[i][j][q] = 0.0f;

    const int lrow = lane & 15;
    const int lkg  = (lane >> 4) * 8;
    const int nch = K >> 5;

    // prefetch chunk 0 into stage 0
    {
        #pragma unroll
        for (int p = 0; p < 2; ++p) {
            int row = srow + p * 64;
            uint32_t so = (uint32_t)(row * SR2B + sq * 16);
            size_t ga = (size_t)(m0 + row) * K + sq * 8;
            size_t gb = (size_t)(n0 + row) * K + sq * 8;
            cpasync16(sbase + so,          Ahi + ga);
            cpasync16(sbase + T2 + so,     Alo + ga);
            cpasync16(sbase + 2*T2 + so,   Whi + gb);
            cpasync16(sbase + 3*T2 + so,   Wlo + gb);
        }
        asm volatile("cp.async.commit_group;" ::: "memory");
    }

    for (int c = 0; c < nch; ++c) {
        if (c + 1 < nch) {
            uint32_t sb = sbase + ((c + 1) & 1) * STAGE2;
            #pragma unroll
            for (int p = 0; p < 2; ++p) {
                int row = srow + p * 64;
                uint32_t so = (uint32_t)(row * SR2B + sq * 16);
                size_t ga = (size_t)(m0 + row) * K + (c + 1) * 32 + sq * 8;
                size_t gb = (size_t)(n0 + row) * K + (c + 1) * 32 + sq * 8;
                cpasync16(sb + so,          Ahi + ga);
                cpasync16(sb + T2 + so,     Alo + ga);
                cpasync16(sb + 2*T2 + so,   Whi + gb);
                cpasync16(sb + 3*T2 + so,   Wlo + gb);
            }
            asm volatile("cp.async.commit_group;" ::: "memory");
            asm volatile("cp.async.wait_group 1;" ::: "memory");
        } else {
            asm volatile("cp.async.wait_group 0;" ::: "memory");
        }
        __syncthreads();

        const uint32_t st = sbase + (c & 1) * STAGE2;
        #pragma unroll
        for (int pass = 0; pass < 3; ++pass) {
            const uint32_t abase = st + (pass == 2 ? T2 : 0) +
                (uint32_t)((wm * 64 + lrow) * SR2B + lkg * 2);
            const uint32_t bbase = st + 2*T2 + (pass == 1 ? T2 : 0) +
                (uint32_t)((wn * 32 + lrow) * SR2B + lkg * 2);
            #pragma unroll
            for (int k16 = 0; k16 < 2; ++k16) {
                uint32_t a[4][4], b[2][4];
                #pragma unroll
                for (int mt = 0; mt < 4; ++mt)
                    ldmx4(a[mt], abase + mt * 16 * SR2B + k16 * 32);
                #pragma unroll
                for (int bh = 0; bh < 2; ++bh)
                    ldmx4(b[bh], bbase + bh * 16 * SR2B + k16 * 32);
                #pragma unroll
                for (int mt = 0; mt < 4; ++mt) {
                    #pragma unroll
                    for (int nt = 0; nt < 4; ++nt) {
                        int bh = nt >> 1, sub = nt & 1;
                        mma16816(acc[mt][nt], a[mt], b[bh][sub], b[bh][sub + 2]);
                    }
                }
            }
        }
        __syncthreads();
    }

    #pragma unroll
    for (int nt = 0; nt < 4; ++nt) {
        int col = n0 + wn * 32 + nt * 8 + (lane & 3) * 2;
        float2 bv = *(const float2*)(bias + col);
        #pragma unroll
        for (int mt = 0; mt < 4; ++mt) {
            int row = m0 + wm * 64 + mt * 16 + (lane >> 2);
            float2 o0 = { acc[mt][nt][0] + bv.x, acc[mt][nt][1] + bv.y };
            float2 o1 = { acc[mt][nt][2] + bv.x, acc[mt][nt][3] + bv.y };
            *(float2*)(C + (size_t)row * G_SZ + col) = o0;
            *(float2*)(C + (size_t)(row + 8) * G_SZ + col) = o1;
        }
    }
}

// ---------------------------------------------------------------------------
// Persistent recurrent scan on tensor cores, v3:
//  - W fragments in registers, hp in registers, bf16 hi/lo exchange (proven)
//  - redundant post-mma sync removed
//  - finalizers also write next layer's A-split (g_ahi/g_alo) when wnext
// ---------------------------------------------------------------------------
#define SROW  264
#define SROWB (SROW * 2)
#define WS_E  (96 * SROW)
#define AS_E  (16 * SROW)
#define SCAN_SMEM (2*WS_E*2 + 2*AS_E*2 + 128*12*4)   // 124416 B

__global__ void __launch_bounds__(256)
gru_scan_kernel(const float* __restrict__ Whh, const float* __restrict__ bhh,
                const float* __restrict__ gx, const float* __restrict__ hinit,
                float* __restrict__ out, float* __restrict__ finals, int wnext)
{
    extern __shared__ char sm[];
    __nv_bfloat16* WSH = (__nv_bfloat16*)sm;          // [96][264]
    __nv_bfloat16* WSL = WSH + WS_E;
    __nv_bfloat16* ASH = WSL + WS_E;                  // [16][264]
    __nv_bfloat16* ASL = ASH + AS_E;
    float* red = (float*)(ASL + AS_E);                // [128][12]

    const int tid = threadIdx.x;
    const int bg = blockIdx.x >> 3;      // 0..15
    const int hg = blockIdx.x & 7;       // 0..7
    const int b0 = bg * 16;
    const int h0 = hg * 32;

    for (int idx = tid; idx < 96 * 256; idx += 256) {
        int j = idx >> 8;
        int k = idx & 255;
        float v = Whh[(size_t)((j >> 5) * 256 + h0 + (j & 31)) * 256 + k];
        __nv_bfloat16 hb = __float2bfloat16(v);
        __nv_bfloat16 lb = __float2bfloat16(v - __bfloat162float(hb));
        WSH[j * SROW + k] = hb;
        WSL[j * SROW + k] = lb;
    }

    const int wid  = tid >> 5;
    const int L    = tid & 31;
    const int wmod = wid & 3;
    const int kb16 = (wid >> 2) * 8;
    const int gr   = L >> 2;
    const int ch   = h0 + wmod * 8 + (L & 3) * 2;

    float2 brv = *(const float2*)(bhh + ch);
    float2 bzv = *(const float2*)(bhh + 256 + ch);
    float2 bnv = *(const float2*)(bhh + 512 + ch);

    const uint32_t aH = smem_u32(ASH) +
        (uint32_t)((L & 15) * SROWB + (L >> 4) * 16);
    const uint32_t aL = aH + (uint32_t)(AS_E * 2);
    const uint32_t bHb = smem_u32(WSH) +
        (uint32_t)((L & 7) * SROWB + ((L >> 3) & 1) * 16);
    const uint32_t bLb = bHb + (uint32_t)(WS_E * 2);

    {
        const float4* src4 = (const float4*)(hinit + (size_t)b0 * 256);
        #pragma unroll
        for (int p = 0; p < 4; ++p) {
            int f = tid + p * 256;
            int row = f >> 6;
            int kq = f & 63;
            float4 v = src4[row * 64 + kq];
            uint2 hiw, low;
            hiw.x = bpack(v.x, v.y, false); hiw.y = bpack(v.z, v.w, false);
            low.x = bpack(v.x, v.y, true);  low.y = bpack(v.z, v.w, true);
            *(uint2*)(ASH + row * SROW + kq * 4) = hiw;
            *(uint2*)(ASL + row * SROW + kq * 4) = low;
        }
    }

    float2 hp0, hp1, pr0, pz0, pn0, pr1, pz1, pn1;
    if (wid < 4) {
        hp0 = *(const float2*)(hinit + (size_t)(b0 + gr) * 256 + ch);
        hp1 = *(const float2*)(hinit + (size_t)(b0 + gr + 8) * 256 + ch);
        const float* q0 = gx + (size_t)(b0 + gr) * G_SZ + ch;
        const float* q1 = gx + (size_t)(b0 + gr + 8) * G_SZ + ch;
        pr0 = *(const float2*)(q0);       pr1 = *(const float2*)(q1);
        pz0 = *(const float2*)(q0 + 256); pz1 = *(const float2*)(q1 + 256);
        pn0 = *(const float2*)(q0 + 512); pn1 = *(const float2*)(q1 + 512);
    }

    __syncthreads();

    uint32_t Bf0[3][8][2], Bf1[3][8][2];
    #pragma unroll
    for (int q = 0; q < 3; ++q) {
        const uint32_t nofs = (uint32_t)((wmod + q * 4) * 8 * SROWB);
        #pragma unroll
        for (int k16 = 0; k16 < 8; ++k16) {
            ldmx2(Bf0[q][k16], bHb + nofs + (kb16 + k16) * 32);
            ldmx2(Bf1[q][k16], bLb + nofs + (kb16 + k16) * 32);
        }
    }

    for (int t = 0; t < T_LEN; ++t) {
        if (t > 0) {
            const uint4* src = (const uint4*)(&g_hex[t & 1][b0][0]);
            #pragma unroll
            for (int p = 0; p < 4; ++p) {
                int f = tid + p * 256;
                int row = f >> 6;
                int q = f & 63;
                uint4 v = __ldcv(src + row * 64 + q);
                __nv_bfloat16* dst = (q < 32)
                    ? (ASH + row * SROW + q * 8)
                    : (ASL + row * SROW + (q - 32) * 8);
                *(uint4*)dst = v;
            }
            __syncthreads();
        }

        float acc[3][4];
        #pragma unroll
        for (int q = 0; q < 3; ++q)
            #pragma unroll
            for (int i = 0; i < 4; ++i) acc[q][i] = 0.0f;

        #pragma unroll
        for (int pass = 0; pass < 3; ++pass) {
            uint32_t aB = (pass == 2) ? aL : aH;
            #pragma unroll
            for (int k16 = 0; k16 < 8; ++k16) {
                uint32_t a[4];
                ldmx4(a, aB + (kb16 + k16) * 32);
                #pragma unroll
                for (int q = 0; q < 3; ++q) {
                    if (pass == 1) mma16816(acc[q], a, Bf1[q][k16][0], Bf1[q][k16][1]);
                    else           mma16816(acc[q], a, Bf0[q][k16][0], Bf0[q][k16][1]);
                }
            }
        }

        if (wid >= 4) {
            float* rp = red + (tid & 127) * 12;
            #pragma unroll
            for (int q = 0; q < 3; ++q)
                #pragma unroll
                for (int i = 0; i < 4; ++i) rp[q * 4 + i] = acc[q][i];
        }
        __syncthreads();

        if (wid < 4) {
            const float* rp = red + tid * 12;
            #pragma unroll
            for (int q = 0; q < 3; ++q)
                #pragma unroll
                for (int i = 0; i < 4; ++i) acc[q][i] += rp[q * 4 + i];

            float rg0 = sigmf(pr0.x + acc[0][0] + brv.x);
            float rg1 = sigmf(pr0.y + acc[0][1] + brv.y);
            float zg0 = sigmf(pz0.x + acc[1][0] + bzv.x);
            float zg1 = sigmf(pz0.y + acc[1][1] + bzv.y);
            float ng0 = tanh_f(pn0.x + rg0 * (acc[2][0] + bnv.x));
            float ng1 = tanh_f(pn0.y + rg1 * (acc[2][1] + bnv.y));
            float2 hv0 = { (1.0f - zg0) * ng0 + zg0 * hp0.x,
                           (1.0f - zg1) * ng1 + zg1 * hp0.y };
            float rg2 = sigmf(pr1.x + acc[0][2] + brv.x);
            float rg3 = sigmf(pr1.y + acc[0][3] + brv.y);
            float zg2 = sigmf(pz1.x + acc[1][2] + bzv.x);
            float zg3 = sigmf(pz1.y + acc[1][3] + bzv.y);
            float ng2 = tanh_f(pn1.x + rg2 * (acc[2][2] + bnv.x));
            float ng3 = tanh_f(pn1.y + rg3 * (acc[2][3] + bnv.y));
            float2 hv1 = { (1.0f - zg2) * ng2 + zg2 * hp1.x,
                           (1.0f - zg3) * ng3 + zg3 * hp1.y };

            hp0 = hv0; hp1 = hv1;

            const size_t r0 = (size_t)t * B_SZ + b0 + gr;
            const size_t r1 = r0 + 8;
            *(float2*)(out + r0 * 256 + ch) = hv0;
            *(float2*)(out + r1 * 256 + ch) = hv1;

            uint32_t w0h = bpack(hv0.x, hv0.y, false);
            uint32_t w0l = bpack(hv0.x, hv0.y, true);
            uint32_t w1h = bpack(hv1.x, hv1.y, false);
            uint32_t w1l = bpack(hv1.x, hv1.y, true);

            if (wnext) {
                // next layer's input A-split (row-major [T*B][256])
                *(uint32_t*)(g_ahi + r0 * 256 + ch) = w0h;
                *(uint32_t*)(g_alo + r0 * 256 + ch) = w0l;
                *(uint32_t*)(g_ahi + r1 * 256 + ch) = w1h;
                *(uint32_t*)(g_alo + r1 * 256 + ch) = w1l;
            }

            if (t == T_LEN - 1) {
                *(float2*)(finals + (size_t)(b0 + gr) * 256 + ch) = hv0;
                *(float2*)(finals + (size_t)(b0 + gr + 8) * 256 + ch) = hv1;
            } else {
                int par = (t + 1) & 1;
                __nv_bfloat16* e0 = &g_hex[par][b0 + gr][0];
                __nv_bfloat16* e1 = &g_hex[par][b0 + gr + 8][0];
                *(uint32_t*)(e0 + ch)       = w0h;
                *(uint32_t*)(e0 + 256 + ch) = w0l;
                *(uint32_t*)(e1 + ch)       = w1h;
                *(uint32_t*)(e1 + 256 + ch) = w1l;

                const float* q0 = gx + ((size_t)(t + 1) * B_SZ + b0 + gr) * G_SZ + ch;
                const float* q1 = gx + ((size_t)(t + 1) * B_SZ + b0 + gr + 8) * G_SZ + ch;
                pr0 = *(const float2*)(q0);       pr1 = *(const float2*)(q1);
                pz0 = *(const float2*)(q0 + 256); pz1 = *(const float2*)(q1 + 256);
                pn0 = *(const float2*)(q0 + 512); pn1 = *(const float2*)(q1 + 512);
            }
        }

        if (t != T_LEN - 1) bg_barrier(bg);
    }
}

// ---------------------------------------------------------------------------
extern "C" void kernel_launch(void* const* d_in, const int* in_sizes, int n_in,
                              void* d_out, int out_size)
{
    const float* x     = (const float*)d_in[0];
    const float* h0    = (const float*)d_in[1];
    const float* Wih0  = (const float*)d_in[2];
    const float* Wih   = (const float*)d_in[3];
    const float* Whh   = (const float*)d_in[4];
    const float* bih   = (const float*)d_in[5];
    const float* bhh   = (const float*)d_in[6];
    float* out = (float*)d_out;

    float *gx_p = nullptr, *buf_p = nullptr;
    __nv_bfloat16 *ahi_p, *alo_p, *whi_p, *wlo_p;
    cudaGetSymbolAddress((void**)&gx_p,  g_gx);
    cudaGetSymbolAddress((void**)&buf_p, g_buf);
    cudaGetSymbolAddress((void**)&ahi_p, g_ahi);
    cudaGetSymbolAddress((void**)&alo_p, g_alo);
    cudaGetSymbolAddress((void**)&whi_p, g_whi);
    cudaGetSymbolAddress((void**)&wlo_p, g_wlo);

    cudaFuncSetAttribute(gru_scan_kernel,
                         cudaFuncAttributeMaxDynamicSharedMemorySize, SCAN_SMEM);
    cudaFuncSetAttribute(gemm_mma_kernel,
                         cudaFuncAttributeMaxDynamicSharedMemorySize, GSM2);

    for (int l = 0; l < L_NUM; ++l) {
        float*       lo  = (l == L_NUM - 1) ? out : buf_p + (size_t)(l & 1) * TBH;
        const int    K   = (l == 0) ? I_SZ : H_SZ;
        const float* Wi  = (l == 0) ? Wih0 : Wih + (size_t)(l - 1) * G_SZ * H_SZ;
        const float* Wh  = Whh + (size_t)l * G_SZ * H_SZ;
        const float* bi  = bih + (size_t)l * G_SZ;
        const float* bh  = bhh + (size_t)l * G_SZ;

        // layer 0: split x and W; layers >=1: A-split already written by
        // previous scan, only split W.
        int mk4 = (l == 0) ? (M_ROWS * I_SZ / 4) : 0;
        int wk4 = G_SZ * K / 4;
        conv_kernel<<<(mk4 + wk4 + 255) / 256, 256>>>(x, Wi, mk4, wk4);

        dim3 gg(G_SZ / 128, M_ROWS / 128);
        gemm_mma_kernel<<<gg, 256, GSM2>>>(ahi_p, alo_p, whi_p, wlo_p,
                                           bi, gx_p, K);

        gru_scan_kernel<<<128, 256, SCAN_SMEM>>>(Wh, bh, gx_p,
                                                 h0 + (size_t)l * BH, lo,
                                                 out + TBH + (size_t)l * BH,
                                                 (l < L_NUM - 1) ? 1 : 0);
    }
}